// round 8
// baseline (speedup 1.0000x reference)
#include <cuda_runtime.h>
#include <cuda_bf16.h>
#include <math.h>
#include <cstdint>

#define S_TOK  8192
#define HID    1024
#define NH     16
#define NKV    8
#define HD     128
#define SEGLEN 1024
#define QKVD   4096
#define OD     2048
#define SCALE  0.08838834764831845f
#define CORR   1024.0f
#define ICORR  (1.0f / 1024.0f)

typedef unsigned long long u64;
typedef unsigned int u32;
typedef unsigned char u8;
typedef __nv_bfloat16 bf16;

// ---------------- scratch -----------------------------------------------
__device__ bf16  g_xh [S_TOK * HID];        // x hi bf16
__device__ u8    g_xf [S_TOK * HID * 2];    // x fp8 [lo*1024 | hi]
__device__ bf16  g_wh [QKVD * HID];         // Wqkv hi bf16
__device__ u8    g_wf [QKVD * HID * 2];     // Wqkv fp8 [hi | lo*1024]
__device__ float g_qkv[S_TOK * QKVD];
__device__ bf16  g_qs [S_TOK * NH  * 256];  // Q split bf16 (attn scores)
__device__ bf16  g_ks [S_TOK * NKV * 256];
__device__ float g_o  [S_TOK * OD];
__device__ bf16  g_oh [S_TOK * OD];
__device__ u8    g_of [S_TOK * OD * 2];
__device__ bf16  g_woh[HID * OD];
__device__ u8    g_wof[HID * OD * 2];

// ---------------- helpers ------------------------------------------------
__device__ __forceinline__ u64 pack2(float a, float b) {
    u64 r; asm("mov.b64 %0,{%1,%2};" : "=l"(r) : "f"(a), "f"(b)); return r;
}
__device__ __forceinline__ void unpack2(u64 v, float& a, float& b) {
    asm("mov.b64 {%0,%1},%2;" : "=f"(a), "=f"(b) : "l"(v));
}
__device__ __forceinline__ void fma2(u64& c, u64 a, u64 b) {
    asm("fma.rn.f32x2 %0,%1,%2,%3;" : "=l"(c) : "l"(a), "l"(b), "l"(c));
}
__device__ __forceinline__ u64 mul2(u64 a, u64 b) {
    u64 r; asm("mul.rn.f32x2 %0,%1,%2;" : "=l"(r) : "l"(a), "l"(b)); return r;
}
__device__ __forceinline__ u32 s2u(const void* p) {
    u32 a; asm("{ .reg .u64 t; cvta.to.shared.u64 t,%1; cvt.u32.u64 %0,t; }"
               : "=r"(a) : "l"(p));
    return a;
}
__device__ __forceinline__ void cp16(u32 dst, const void* src) {
    asm volatile("cp.async.cg.shared.global [%0],[%1],16;" :: "r"(dst), "l"(src));
}
__device__ __forceinline__ void cp_commit() {
    asm volatile("cp.async.commit_group;" ::: "memory");
}
__device__ __forceinline__ void ldsm_x4(u32* r, u32 addr) {
    asm volatile("ldmatrix.sync.aligned.m8n8.x4.shared.b16 {%0,%1,%2,%3},[%4];"
                 : "=r"(r[0]), "=r"(r[1]), "=r"(r[2]), "=r"(r[3]) : "r"(addr));
}
__device__ __forceinline__ void mma16816(float* d, const u32* a, const u32* b) {
    asm volatile(
        "mma.sync.aligned.m16n8k16.row.col.f32.bf16.bf16.f32 "
        "{%0,%1,%2,%3},{%4,%5,%6,%7},{%8,%9},{%0,%1,%2,%3};"
        : "+f"(d[0]), "+f"(d[1]), "+f"(d[2]), "+f"(d[3])
        : "r"(a[0]), "r"(a[1]), "r"(a[2]), "r"(a[3]), "r"(b[0]), "r"(b[1]));
}
__device__ __forceinline__ void qmma16832(float* d, const u32* a, const u32* b) {
    asm volatile(
        "mma.sync.aligned.m16n8k32.row.col.f32.e4m3.e4m3.f32 "
        "{%0,%1,%2,%3},{%4,%5,%6,%7},{%8,%9},{%0,%1,%2,%3};"
        : "+f"(d[0]), "+f"(d[1]), "+f"(d[2]), "+f"(d[3])
        : "r"(a[0]), "r"(a[1]), "r"(a[2]), "r"(a[3]), "r"(b[0]), "r"(b[1]));
}
// pack 4 floats -> 4 e4m3 bytes (byte i = f[i], little-endian)
__device__ __forceinline__ u32 packe4(float f0, float f1, float f2, float f3) {
    unsigned short h0, h1;
    asm("cvt.rn.satfinite.e4m3x2.f32 %0,%1,%2;" : "=h"(h0) : "f"(f1), "f"(f0));
    asm("cvt.rn.satfinite.e4m3x2.f32 %0,%1,%2;" : "=h"(h1) : "f"(f3), "f"(f2));
    return (u32)h0 | ((u32)h1 << 16);
}

// ---------------------------------------------------------------------------
// split conversion: src fp32 [M,K] -> dh bf16 [M,K] (hi), df e4m3 [M,2K]
//   A side (isB=0): df = [ lo*1024 | hi ]
//   B side (isB=1): df = [ hi | lo*1024 ]
// ---------------------------------------------------------------------------
__global__ __launch_bounds__(256) void cvt_split(
    const float* __restrict__ src, bf16* __restrict__ dh, u8* __restrict__ df,
    int K, int isB, int total4)
{
    int i = blockIdx.x * blockDim.x + threadIdx.x;
    if (i >= total4) return;
    int perRow = K >> 2;
    int row = i / perRow;
    int c4 = (i - row * perRow) << 2;
    float4 v = *(const float4*)(src + (size_t)row * K + c4);
    float f[4] = {v.x, v.y, v.z, v.w};
    float lo[4];
    u64 hp = 0;
#pragma unroll
    for (int j = 0; j < 4; j++) {
        bf16 hb = __float2bfloat16(f[j]);
        lo[j] = (f[j] - __bfloat162float(hb)) * CORR;
        hp |= (u64)(*(unsigned short*)&hb) << (16 * j);
    }
    *(u64*)(dh + (size_t)row * K + c4) = hp;
    u32 hi8 = packe4(f[0], f[1], f[2], f[3]);
    u32 lo8 = packe4(lo[0], lo[1], lo[2], lo[3]);
    u8* d = df + (size_t)row * (2 * K) + c4;
    *(u32*)d       = isB ? hi8 : lo8;
    *(u32*)(d + K) = isB ? lo8 : hi8;
}

// ---------------------------------------------------------------------------
// Hybrid fp8+bf16 GEMM: C[M,N] = A[M,K] @ B[N,K]^T  (fp32 result)
// Phase 1 (chunks 0..NB-1):  e4m3 correction pass over the fp8 K-extension.
// Boundary: acc *= 1/1024.
// Phase 2 (chunks NB..2NB-1): bf16 hi*hi pass.
// CTA 128x128, 8 warps (2Mx4N), BK = 128 bytes, 3-stage cp.async.
// Both matrices have row stride 2K BYTES in both phases.
// ---------------------------------------------------------------------------
#define GSTAGE 32768
#define GEMM_SMEM (3 * GSTAGE)

__global__ __launch_bounds__(256) void gemm_mma(
    const u8* __restrict__ Af, const u8* __restrict__ Bf,
    const bf16* __restrict__ Ah, const bf16* __restrict__ Bh,
    float* __restrict__ C, int N, int K)
{
    extern __shared__ char smc[];
    const u32 smb = s2u(smc);
    const int tid = threadIdx.x;
    const int warp = tid >> 5, lane = tid & 31;
    const int wM = warp >> 2, wN = warp & 3;
    const int m0 = blockIdx.y << 7, n0 = blockIdx.x << 7;
    const int NB = K >> 6;
    const int total = 2 * NB;
    const size_t strB = 2 * (size_t)K;   // bytes per row (both phases)

    const char* Afc = (const char*)Af + (size_t)m0 * strB;
    const char* Ahc = (const char*)Ah + (size_t)m0 * strB;
    const char* Bfc = (const char*)Bf + (size_t)n0 * strB;
    const char* Bhc = (const char*)Bh + (size_t)n0 * strB;

    float acc[4][4][4];
#pragma unroll
    for (int a = 0; a < 4; a++)
#pragma unroll
        for (int b = 0; b < 4; b++)
#pragma unroll
            for (int c = 0; c < 4; c++) acc[a][b][c] = 0.f;

    auto load_stage = [&](int st, int ch) {
        const char* Ab = (ch < NB) ? (Afc + ch * 128) : (Ahc + (ch - NB) * 128);
        const char* Bb = (ch < NB) ? (Bfc + ch * 128) : (Bhc + (ch - NB) * 128);
        u32 sa = smb + st * GSTAGE;
        u32 sb = sa + 16384;
#pragma unroll
        for (int j = 0; j < 4; j++) {
            int q = tid + j * 256;
            int r = q >> 3, c = q & 7;
            cp16(sa + r * 128 + ((c ^ (r & 7)) << 4), Ab + (size_t)r * strB + c * 16);
        }
#pragma unroll
        for (int j = 0; j < 4; j++) {
            int q = tid + j * 256;
            int r = q >> 3, c = q & 7;
            cp16(sb + r * 128 + ((c ^ (r & 7)) << 4), Bb + (size_t)r * strB + c * 16);
        }
        cp_commit();
    };

    load_stage(0, 0);
    load_stage(1, 1);

    for (int i = 0; i < total; i++) {
        int s = i % 3;
        asm volatile("cp.async.wait_group 1;" ::: "memory");
        __syncthreads();
        if (i + 2 < total) load_stage((i + 2) % 3, i + 2);
        else cp_commit();

        if (i == NB) {   // all fp8 corrections accumulated -> scale down
#pragma unroll
            for (int a = 0; a < 4; a++)
#pragma unroll
                for (int b = 0; b < 4; b++)
#pragma unroll
                    for (int c = 0; c < 4; c++) acc[a][b][c] *= ICORR;
        }
        bool f8 = (i < NB);

        u32 sa = smb + s * GSTAGE;
        u32 sb = sa + 16384;
#pragma unroll
        for (int kk = 0; kk < 4; kk++) {
            u32 afr[4][4], bfr[2][4];
#pragma unroll
            for (int mt = 0; mt < 4; mt++) {
                int row = wM * 64 + mt * 16 + (lane & 15);
                int ch = kk * 2 + (lane >> 4);
                ldsm_x4(afr[mt], sa + row * 128 + ((ch ^ (row & 7)) << 4));
            }
#pragma unroll
            for (int p = 0; p < 2; p++) {
                int row = wN * 32 + p * 16 + ((lane >> 4) << 3) + (lane & 7);
                int ch = kk * 2 + ((lane >> 3) & 1);
                ldsm_x4(bfr[p], sb + row * 128 + ((ch ^ (row & 7)) << 4));
            }
            if (f8) {
#pragma unroll
                for (int mt = 0; mt < 4; mt++)
#pragma unroll
                    for (int nt = 0; nt < 4; nt++)
                        qmma16832(acc[mt][nt], afr[mt], &bfr[nt >> 1][(nt & 1) * 2]);
            } else {
#pragma unroll
                for (int mt = 0; mt < 4; mt++)
#pragma unroll
                    for (int nt = 0; nt < 4; nt++)
                        mma16816(acc[mt][nt], afr[mt], &bfr[nt >> 1][(nt & 1) * 2]);
            }
        }
    }

    int g = lane >> 2, t = lane & 3;
#pragma unroll
    for (int mt = 0; mt < 4; mt++) {
        int r0 = m0 + wM * 64 + mt * 16 + g;
#pragma unroll
        for (int nt = 0; nt < 4; nt++) {
            int cc = n0 + wN * 32 + nt * 8 + t * 2;
            *(float2*)(C + (size_t)r0 * N + cc) =
                make_float2(acc[mt][nt][0], acc[mt][nt][1]);
            *(float2*)(C + (size_t)(r0 + 8) * N + cc) =
                make_float2(acc[mt][nt][2], acc[mt][nt][3]);
        }
    }
}

// ---------------------------------------------------------------------------
// RMSNorm + multimodal RoPE -> split bf16 Q,K (for attention scores)
// ---------------------------------------------------------------------------
__global__ __launch_bounds__(256) void norm_rope_kernel(
    const float* __restrict__ qkv, bf16* __restrict__ qsp, bf16* __restrict__ ksp,
    const float* __restrict__ cosT, const float* __restrict__ sinT,
    const float* __restrict__ qw, const float* __restrict__ kw)
{
    int gw = (blockIdx.x * blockDim.x + threadIdx.x) >> 5;
    int lane = threadIdx.x & 31;
    if (gw >= S_TOK * (NH + NKV)) return;
    int s = gw / (NH + NKV);
    int h = gw - s * (NH + NKV);

    const float* base; const float* w; bf16* dst;
    if (h < NH) {
        base = qkv + (size_t)s * QKVD + h * HD;               w = qw;
        dst = qsp + ((size_t)s * NH + h) * 256;
    } else {
        base = qkv + (size_t)s * QKVD + 2048 + (h - NH) * HD; w = kw;
        dst = ksp + ((size_t)s * NKV + (h - NH)) * 256;
    }

    float4 x = *(const float4*)(base + lane * 4);
    float ss = x.x * x.x + x.y * x.y + x.z * x.z + x.w * x.w;
#pragma unroll
    for (int m = 16; m > 0; m >>= 1) ss += __shfl_xor_sync(0xffffffffu, ss, m);
    float r = rsqrtf(ss * (1.0f / 128.0f) + 1e-6f);

    float4 wv = *(const float4*)(w + lane * 4);
    float xn0 = x.x * r * wv.x, xn1 = x.y * r * wv.y;
    float xn2 = x.z * r * wv.z, xn3 = x.w * r * wv.w;

    float p0 = __shfl_xor_sync(0xffffffffu, xn0, 16);
    float p1 = __shfl_xor_sync(0xffffffffu, xn1, 16);
    float p2 = __shfl_xor_sync(0xffffffffu, xn2, 16);
    float p3 = __shfl_xor_sync(0xffffffffu, xn3, 16);
    float sgn = (lane < 16) ? -1.0f : 1.0f;

    size_t toff = ((lane < 16) ? (size_t)0 : (size_t)S_TOK * HD)
                + (size_t)s * HD + lane * 4;
    float4 cv = *(const float4*)(cosT + toff);
    float4 sv = *(const float4*)(sinT + toff);

    float ov[4];
    ov[0] = xn0 * cv.x + sgn * p0 * sv.x;
    ov[1] = xn1 * cv.y + sgn * p1 * sv.y;
    ov[2] = xn2 * cv.z + sgn * p2 * sv.z;
    ov[3] = xn3 * cv.w + sgn * p3 * sv.w;

    u64 hp = 0, lp = 0;
#pragma unroll
    for (int j = 0; j < 4; j++) {
        bf16 hb = __float2bfloat16(ov[j]);
        bf16 lb = __float2bfloat16(ov[j] - __bfloat162float(hb));
        hp |= (u64)(*(unsigned short*)&hb) << (16 * j);
        lp |= (u64)(*(unsigned short*)&lb) << (16 * j);
    }
    *(u64*)(dst + lane * 4)       = hp;
    *(u64*)(dst + 128 + lane * 4) = lp;
}

// ---------------------------------------------------------------------------
// Warp-specialized flash attention: 4 S-warps + 8 V-warps (384 threads).
// ---------------------------------------------------------------------------
#define AQS 0
#define AKS 32768
#define AVS 98304
#define APF 163840
#define AAF 198656
#define ALF 199168
#define ATT_SMEM 199424

__global__ __launch_bounds__(384) void attn_tc(
    const bf16* __restrict__ qs, const bf16* __restrict__ ks,
    const float* __restrict__ qkv, float* __restrict__ o)
{
    extern __shared__ char sm[];
    const u32 smb = s2u(sm);
    float* Pf = (float*)(sm + APF);
    float* Af = (float*)(sm + AAF);
    float* Lf = (float*)(sm + ALF);

    const int tid = threadIdx.x;
    const int warp = tid >> 5, lane = tid & 31;
    const bool isS = warp < 4;
    const int qt = blockIdx.x, seg = blockIdx.y, h = blockIdx.z;
    const int hkv = h >> 1;

    const bf16* Qg = qs + ((size_t)(seg * SEGLEN + qt * 64) * NH + h) * 256;
    const bf16* Kg = ks + ((size_t)(seg * SEGLEN) * NKV + hkv) * 256;
    const float* Vg = qkv + (size_t)(seg * SEGLEN) * QKVD + 3072 + hkv * HD;

    // prologue: Q (all 384 threads, guarded), K0 (S), V0 (V)
#pragma unroll
    for (int j = 0; j < 6; j++) {
        int q = tid + j * 384;
        if (q < 2048) {
            int r = q >> 5, c = q & 31;
            cp16(smb + AQS + r * 512 + ((c ^ (r & 7)) << 4),
                 Qg + (size_t)r * (NH * 256) + c * 8);
        }
    }
    cp_commit();
    if (isS) {
#pragma unroll
        for (int j = 0; j < 16; j++) {
            int q = tid + j * 128;
            int r = q >> 5, c = q & 31;
            cp16(smb + AKS + r * 512 + ((c ^ (r & 7)) << 4),
                 Kg + (size_t)r * (NKV * 256) + c * 8);
        }
        cp_commit();
    } else {
        int vt = tid - 128;
#pragma unroll
        for (int j = 0; j < 8; j++) {
            int q = vt + j * 256;
            int r = q >> 5, c = q & 31;
            cp16(smb + AVS + r * 512 + c * 16, Vg + (size_t)r * QKVD + c * 4);
        }
        cp_commit();
    }

    const int g = lane >> 2, t = lane & 3;
    float m0 = -INFINITY, m1 = -INFINITY, l0 = 0.f, l1 = 0.f;   // S state
    u64 O2[4][4];                                                // V state
#pragma unroll
    for (int i = 0; i < 4; i++)
#pragma unroll
        for (int j = 0; j < 4; j++) O2[i][j] = 0ULL;
    const int vt = tid - 128;
    const int tx = vt & 15, ty = vt >> 4;   // ty in [0,16)

    for (int it = 0; it <= 16; it++) {
        asm volatile("cp.async.wait_group 0;" ::: "memory");
        __syncthreads();

        if (isS && it < 16) {
            if (it + 1 < 16) {
                u32 kd = smb + AKS + ((it + 1) & 1) * 32768;
#pragma unroll
                for (int j = 0; j < 16; j++) {
                    int q = tid + j * 128;
                    int r = q >> 5, c = q & 31;
                    cp16(kd + r * 512 + ((c ^ (r & 7)) << 4),
                         Kg + (size_t)((it + 1) * 64 + r) * (NKV * 256) + c * 8);
                }
                cp_commit();
            }
            u32 kb = smb + AKS + (it & 1) * 32768;
            float acc[8][4];
#pragma unroll
            for (int n = 0; n < 8; n++)
#pragma unroll
                for (int c = 0; c < 4; c++) acc[n][c] = 0.f;

            const int ABASE[3] = {0, 16, 0};
            const int BBASE[3] = {0, 0, 16};
#pragma unroll
            for (int p = 0; p < 3; p++) {
#pragma unroll
                for (int k = 0; k < 8; k++) {
                    u32 afr[4], bfr[4][4];
                    int ar = warp * 16 + (lane & 15);
                    int ac = ABASE[p] + 2 * k + (lane >> 4);
                    ldsm_x4(afr, smb + AQS + ar * 512 + ((ac ^ (ar & 7)) << 4));
#pragma unroll
                    for (int pg = 0; pg < 4; pg++) {
                        int br = pg * 16 + ((lane >> 4) << 3) + (lane & 7);
                        int bc = BBASE[p] + 2 * k + ((lane >> 3) & 1);
                        ldsm_x4(bfr[pg], kb + br * 512 + ((bc ^ (br & 7)) << 4));
                    }
#pragma unroll
                    for (int nt = 0; nt < 8; nt++)
                        mma16816(acc[nt], afr, &bfr[nt >> 1][(nt & 1) * 2]);
                }
            }
            float mx0 = -INFINITY, mx1 = -INFINITY;
#pragma unroll
            for (int n = 0; n < 8; n++) {
#pragma unroll
                for (int c = 0; c < 4; c++) acc[n][c] *= SCALE;
                mx0 = fmaxf(mx0, fmaxf(acc[n][0], acc[n][1]));
                mx1 = fmaxf(mx1, fmaxf(acc[n][2], acc[n][3]));
            }
            mx0 = fmaxf(mx0, __shfl_xor_sync(0xffffffffu, mx0, 1));
            mx0 = fmaxf(mx0, __shfl_xor_sync(0xffffffffu, mx0, 2));
            mx1 = fmaxf(mx1, __shfl_xor_sync(0xffffffffu, mx1, 1));
            mx1 = fmaxf(mx1, __shfl_xor_sync(0xffffffffu, mx1, 2));
            float mn0 = fmaxf(m0, mx0), mn1 = fmaxf(m1, mx1);
            float a0 = __expf(m0 - mn0), a1 = __expf(m1 - mn1);
            m0 = mn0; m1 = mn1;
            float s0 = 0.f, s1 = 0.f;
#pragma unroll
            for (int n = 0; n < 8; n++) {
                acc[n][0] = __expf(acc[n][0] - mn0); s0 += acc[n][0];
                acc[n][1] = __expf(acc[n][1] - mn0); s0 += acc[n][1];
                acc[n][2] = __expf(acc[n][2] - mn1); s1 += acc[n][2];
                acc[n][3] = __expf(acc[n][3] - mn1); s1 += acc[n][3];
            }
            s0 += __shfl_xor_sync(0xffffffffu, s0, 1);
            s0 += __shfl_xor_sync(0xffffffffu, s0, 2);
            s1 += __shfl_xor_sync(0xffffffffu, s1, 1);
            s1 += __shfl_xor_sync(0xffffffffu, s1, 2);
            l0 = l0 * a0 + s0;
            l1 = l1 * a1 + s1;

            int r0 = warp * 16 + g, r1 = r0 + 8;
            float* Pb = Pf + (it & 1) * (64 * 68);
#pragma unroll
            for (int n = 0; n < 8; n++) {
                *(float2*)&Pb[r0 * 68 + n * 8 + t * 2] = make_float2(acc[n][0], acc[n][1]);
                *(float2*)&Pb[r1 * 68 + n * 8 + t * 2] = make_float2(acc[n][2], acc[n][3]);
            }
            if (t == 0) {
                Af[(it & 1) * 64 + r0] = a0;
                Af[(it & 1) * 64 + r1] = a1;
                if (it == 15) { Lf[r0] = l0; Lf[r1] = l1; }
            }
        }

        if (!isS && it > 0) {
            int j = it - 1;
            if (it < 16) {
                u32 vd = smb + AVS + (it & 1) * 32768;
#pragma unroll
                for (int jj = 0; jj < 8; jj++) {
                    int q = vt + jj * 256;
                    int r = q >> 5, c = q & 31;
                    cp16(vd + r * 512 + c * 16,
                         Vg + (size_t)(it * 64 + r) * QKVD + c * 4);
                }
                cp_commit();
            }
            const float* Pb = Pf + (j & 1) * (64 * 68);
            const char* Vb = sm + AVS + (j & 1) * 32768;
#pragma unroll
            for (int ii = 0; ii < 4; ii++) {
                float a = Af[(j & 1) * 64 + ty * 4 + ii];
                u64 ad = pack2(a, a);
#pragma unroll
                for (int c = 0; c < 4; c++) O2[ii][c] = mul2(O2[ii][c], ad);
            }
#pragma unroll 4
            for (int j4 = 0; j4 < 16; j4++) {
                float pv[4][4];
#pragma unroll
                for (int ii = 0; ii < 4; ii++) {
                    float4 tmp = *(const float4*)&Pb[(ty * 4 + ii) * 68 + j4 * 4];
                    pv[ii][0] = tmp.x; pv[ii][1] = tmp.y;
                    pv[ii][2] = tmp.z; pv[ii][3] = tmp.w;
                }
#pragma unroll
                for (int e = 0; e < 4; e++) {
                    const u64* vr = (const u64*)(Vb + ((j4 * 4 + e) * 128 + tx * 8) * 4);
                    u64 v0 = vr[0], v1 = vr[1], v2 = vr[2], v3 = vr[3];
#pragma unroll
                    for (int ii = 0; ii < 4; ii++) {
                        u64 pd = pack2(pv[ii][e], pv[ii][e]);
                        fma2(O2[ii][0], pd, v0);
                        fma2(O2[ii][1], pd, v1);
                        fma2(O2[ii][2], pd, v2);
                        fma2(O2[ii][3], pd, v3);
                    }
                }
            }
        }
    }

    if (!isS) {
#pragma unroll
        for (int ii = 0; ii < 4; ii++) {
            int row = ty * 4 + ii;
            float inv = 1.0f / Lf[row];
            float ov[8];
#pragma unroll
            for (int c = 0; c < 4; c++) {
                float lo, hi; unpack2(O2[ii][c], lo, hi);
                ov[2 * c] = lo * inv; ov[2 * c + 1] = hi * inv;
            }
            float* op = o + (size_t)(seg * SEGLEN + qt * 64 + row) * OD + h * HD + tx * 8;
            *(float4*)op       = make_float4(ov[0], ov[1], ov[2], ov[3]);
            *(float4*)(op + 4) = make_float4(ov[4], ov[5], ov[6], ov[7]);
        }
    }
}

// ---------------------------------------------------------------------------
extern "C" void kernel_launch(void* const* d_in, const int* in_sizes, int n_in,
                              void* d_out, int out_size)
{
    const float* x    = (const float*)d_in[0];
    const float* cosT = (const float*)d_in[2];
    const float* sinT = (const float*)d_in[3];
    const float* Wq   = (const float*)d_in[4];
    const float* Wk   = (const float*)d_in[5];
    const float* Wv   = (const float*)d_in[6];
    const float* Wo   = (const float*)d_in[7];
    const float* qw   = (const float*)d_in[8];
    const float* kw   = (const float*)d_in[9];
    float* out = (float*)d_out;

    bf16 *xh, *wh, *oh, *woh, *qsp, *ksp;
    u8 *xf, *wf, *of, *wof;
    float *qkv, *op;
    cudaGetSymbolAddress((void**)&xh,  g_xh);
    cudaGetSymbolAddress((void**)&xf,  g_xf);
    cudaGetSymbolAddress((void**)&wh,  g_wh);
    cudaGetSymbolAddress((void**)&wf,  g_wf);
    cudaGetSymbolAddress((void**)&qkv, g_qkv);
    cudaGetSymbolAddress((void**)&op,  g_o);
    cudaGetSymbolAddress((void**)&oh,  g_oh);
    cudaGetSymbolAddress((void**)&of,  g_of);
    cudaGetSymbolAddress((void**)&woh, g_woh);
    cudaGetSymbolAddress((void**)&wof, g_wof);
    cudaGetSymbolAddress((void**)&qsp, g_qs);
    cudaGetSymbolAddress((void**)&ksp, g_ks);

    cudaFuncSetAttribute(gemm_mma,
        cudaFuncAttributeMaxDynamicSharedMemorySize, GEMM_SMEM);
    cudaFuncSetAttribute(attn_tc,
        cudaFuncAttributeMaxDynamicSharedMemorySize, ATT_SMEM);

    // launches 0-4: conversions (launch 5 = QKV gemm for ncu -s 5)
    {
        int t4 = S_TOK * HID / 4;
        cvt_split<<<(t4 + 255) / 256, 256>>>(x, xh, xf, HID, 0, t4);
        t4 = 2048 * HID / 4;
        cvt_split<<<(t4 + 255) / 256, 256>>>(Wq, wh, wf, HID, 1, t4);
        t4 = 1024 * HID / 4;
        cvt_split<<<(t4 + 255) / 256, 256>>>(Wk, wh + (size_t)2048 * HID,
                                             wf + (size_t)2048 * HID * 2, HID, 1, t4);
        cvt_split<<<(t4 + 255) / 256, 256>>>(Wv, wh + (size_t)3072 * HID,
                                             wf + (size_t)3072 * HID * 2, HID, 1, t4);
        t4 = HID * OD / 4;
        cvt_split<<<(t4 + 255) / 256, 256>>>(Wo, woh, wof, OD, 1, t4);
    }

    // QKV projection (fp8 corrections + bf16 hi)
    gemm_mma<<<dim3(QKVD / 128, S_TOK / 128), 256, GEMM_SMEM>>>(
        xf, wf, xh, wh, qkv, QKVD, HID);

    // RMSNorm + RoPE -> split bf16 Q,K
    int warps = S_TOK * (NH + NKV);
    norm_rope_kernel<<<(warps * 32 + 255) / 256, 256>>>(qkv, qsp, ksp, cosT, sinT, qw, kw);

    // attention (4 S-warps + 8 V-warps)
    attn_tc<<<dim3(16, 8, 16), 384, ATT_SMEM>>>(qsp, ksp, qkv, op);

    // output projection
    {
        int t4 = S_TOK * OD / 4;
        cvt_split<<<(t4 + 255) / 256, 256>>>(op, oh, of, OD, 0, t4);
    }
    gemm_mma<<<dim3(HID / 128, S_TOK / 128), 256, GEMM_SMEM>>>(
        of, wof, oh, woh, out, HID, OD);
}

// round 9
// speedup vs baseline: 1.3680x; 1.3680x over previous
#include <cuda_runtime.h>
#include <cuda_bf16.h>
#include <cuda_fp16.h>
#include <math.h>
#include <cstdint>

#define S_TOK  8192
#define HID    1024
#define NH     16
#define NKV    8
#define HD     128
#define SEGLEN 1024
#define QKVD   4096            // combined q|k|v output row
#define OD     2048            // attention output row
#define KP1    2048            // 2*1024 split-K (QKV proj, fp16 2-term)
#define KP2    4096            // 2*2048 split-K (out proj, fp16 2-term)
#define SCALE  0.08838834764831845f

typedef unsigned long long u64;
typedef unsigned int u32;
typedef __nv_bfloat16 bf16;
typedef __half f16;

// ---------------- scratch (static device arrays, no runtime alloc) ----------
__device__ f16   g_x2 [S_TOK * KP1];      // x split fp16 [8192,2048]  hi|lo
__device__ f16   g_w2 [QKVD  * KP1];      // Wqkv split   [4096,2048]  hi|hi
__device__ float g_qkv[S_TOK * QKVD];     // q|k|v fp32
__device__ bf16  g_qs [S_TOK * NH  * 256];// Q split bf16 [S][16][hi128|lo128]
__device__ bf16  g_ks [S_TOK * NKV * 256];// K split bf16 [S][8][hi128|lo128]
__device__ float g_o  [S_TOK * OD];       // attention out fp32
__device__ f16   g_o2 [S_TOK * KP2];      // attn out split [8192,4096] hi|lo
__device__ f16   g_wo2[HID   * KP2];      // Wo split [1024,4096] hi|hi

// ---------------- small helpers --------------------------------------------
__device__ __forceinline__ u64 pack2(float a, float b) {
    u64 r; asm("mov.b64 %0,{%1,%2};" : "=l"(r) : "f"(a), "f"(b)); return r;
}
__device__ __forceinline__ void unpack2(u64 v, float& a, float& b) {
    asm("mov.b64 {%0,%1},%2;" : "=f"(a), "=f"(b) : "l"(v));
}
__device__ __forceinline__ void fma2(u64& c, u64 a, u64 b) {
    asm("fma.rn.f32x2 %0,%1,%2,%3;" : "=l"(c) : "l"(a), "l"(b), "l"(c));
}
__device__ __forceinline__ u64 mul2(u64 a, u64 b) {
    u64 r; asm("mul.rn.f32x2 %0,%1,%2;" : "=l"(r) : "l"(a), "l"(b)); return r;
}
__device__ __forceinline__ u32 s2u(const void* p) {
    u32 a; asm("{ .reg .u64 t; cvta.to.shared.u64 t,%1; cvt.u32.u64 %0,t; }"
               : "=r"(a) : "l"(p));
    return a;
}
__device__ __forceinline__ void cp16(u32 dst, const void* src) {
    asm volatile("cp.async.cg.shared.global [%0],[%1],16;" :: "r"(dst), "l"(src));
}
__device__ __forceinline__ void cp_commit() {
    asm volatile("cp.async.commit_group;" ::: "memory");
}
__device__ __forceinline__ void ldsm_x4(u32* r, u32 addr) {
    asm volatile("ldmatrix.sync.aligned.m8n8.x4.shared.b16 {%0,%1,%2,%3},[%4];"
                 : "=r"(r[0]), "=r"(r[1]), "=r"(r[2]), "=r"(r[3]) : "r"(addr));
}
__device__ __forceinline__ void mma_bf16(float* d, const u32* a, const u32* b) {
    asm volatile(
        "mma.sync.aligned.m16n8k16.row.col.f32.bf16.bf16.f32 "
        "{%0,%1,%2,%3},{%4,%5,%6,%7},{%8,%9},{%0,%1,%2,%3};"
        : "+f"(d[0]), "+f"(d[1]), "+f"(d[2]), "+f"(d[3])
        : "r"(a[0]), "r"(a[1]), "r"(a[2]), "r"(a[3]), "r"(b[0]), "r"(b[1]));
}
__device__ __forceinline__ void mma_f16(float* d, const u32* a, const u32* b) {
    asm volatile(
        "mma.sync.aligned.m16n8k16.row.col.f32.f16.f16.f32 "
        "{%0,%1,%2,%3},{%4,%5,%6,%7},{%8,%9},{%0,%1,%2,%3};"
        : "+f"(d[0]), "+f"(d[1]), "+f"(d[2]), "+f"(d[3])
        : "r"(a[0]), "r"(a[1]), "r"(a[2]), "r"(a[3]), "r"(b[0]), "r"(b[1]));
}

// ---------------------------------------------------------------------------
// fp16 2-term split: src fp32 [M,K] -> dst f16 [M,2K]
//   A side (isB=0): [ hi | lo ]
//   B side (isB=1): [ hi | hi ]
// ---------------------------------------------------------------------------
__global__ __launch_bounds__(256) void cvt_split(
    const float* __restrict__ src, f16* __restrict__ dst,
    int K, int isB, int total4)
{
    int i = blockIdx.x * blockDim.x + threadIdx.x;
    if (i >= total4) return;
    int perRow = K >> 2;
    int row = i / perRow;
    int c4 = (i - row * perRow) << 2;
    float4 v = *(const float4*)(src + (size_t)row * K + c4);
    float f[4] = {v.x, v.y, v.z, v.w};
    u64 hp = 0, lp = 0;
#pragma unroll
    for (int j = 0; j < 4; j++) {
        f16 hb = __float2half(f[j]);
        f16 lb = __float2half(f[j] - __half2float(hb));
        hp |= (u64)(*(unsigned short*)&hb) << (16 * j);
        lp |= (u64)(*(unsigned short*)&lb) << (16 * j);
    }
    f16* d = dst + (size_t)row * (2 * K) + c4;
    *(u64*)d       = hp;
    *(u64*)(d + K) = isB ? hp : lp;
}

// ---------------------------------------------------------------------------
// mma.sync GEMM (R4-proven shape): C[M,N] fp32 = A[M,Kp] f16 @ B[N,Kp]^T f16
// CTA 128x128, 8 warps (2Mx4N), BK=64, 3-stage cp.async.
// ---------------------------------------------------------------------------
#define GSTAGE 32768
#define GEMM_SMEM (3 * GSTAGE)   // 98304

__global__ __launch_bounds__(256) void gemm_mma(
    const f16* __restrict__ A, const f16* __restrict__ B,
    float* __restrict__ C, int N, int Kp)
{
    extern __shared__ char smc[];
    const u32 smb = s2u(smc);
    const int tid = threadIdx.x;
    const int warp = tid >> 5, lane = tid & 31;
    const int wM = warp >> 2, wN = warp & 3;
    const int m0 = blockIdx.y << 7, n0 = blockIdx.x << 7;
    const int chunks = Kp >> 6;

    const f16* Ag = A + (size_t)m0 * Kp;
    const f16* Bg = B + (size_t)n0 * Kp;

    float acc[4][4][4];
#pragma unroll
    for (int a = 0; a < 4; a++)
#pragma unroll
        for (int b = 0; b < 4; b++)
#pragma unroll
            for (int c = 0; c < 4; c++) acc[a][b][c] = 0.f;

    auto load_stage = [&](int st, int ch) {
        u32 sa = smb + st * GSTAGE;
        u32 sb = sa + 16384;
#pragma unroll
        for (int j = 0; j < 4; j++) {
            int q = tid + j * 256;
            int r = q >> 3, c = q & 7;
            cp16(sa + r * 128 + ((c ^ (r & 7)) << 4),
                 Ag + (size_t)r * Kp + ch * 64 + c * 8);
        }
#pragma unroll
        for (int j = 0; j < 4; j++) {
            int q = tid + j * 256;
            int r = q >> 3, c = q & 7;
            cp16(sb + r * 128 + ((c ^ (r & 7)) << 4),
                 Bg + (size_t)r * Kp + ch * 64 + c * 8);
        }
        cp_commit();
    };

    load_stage(0, 0);
    load_stage(1, 1);

    for (int i = 0; i < chunks; i++) {
        int s = i % 3;
        asm volatile("cp.async.wait_group 1;" ::: "memory");
        __syncthreads();
        if (i + 2 < chunks) load_stage((i + 2) % 3, i + 2);
        else cp_commit();

        u32 sa = smb + s * GSTAGE;
        u32 sb = sa + 16384;
#pragma unroll
        for (int kk = 0; kk < 4; kk++) {
            u32 afr[4][4], bfr[2][4];
#pragma unroll
            for (int mt = 0; mt < 4; mt++) {
                int row = wM * 64 + mt * 16 + (lane & 15);
                int ch = kk * 2 + (lane >> 4);
                ldsm_x4(afr[mt], sa + row * 128 + ((ch ^ (row & 7)) << 4));
            }
#pragma unroll
            for (int p = 0; p < 2; p++) {
                int row = wN * 32 + p * 16 + ((lane >> 4) << 3) + (lane & 7);
                int ch = kk * 2 + ((lane >> 3) & 1);
                ldsm_x4(bfr[p], sb + row * 128 + ((ch ^ (row & 7)) << 4));
            }
#pragma unroll
            for (int mt = 0; mt < 4; mt++)
#pragma unroll
                for (int nt = 0; nt < 4; nt++)
                    mma_f16(acc[mt][nt], afr[mt], &bfr[nt >> 1][(nt & 1) * 2]);
        }
    }

    int g = lane >> 2, t = lane & 3;
#pragma unroll
    for (int mt = 0; mt < 4; mt++) {
        int r0 = m0 + wM * 64 + mt * 16 + g;
#pragma unroll
        for (int nt = 0; nt < 4; nt++) {
            int cc = n0 + wN * 32 + nt * 8 + t * 2;
            *(float2*)(C + (size_t)r0 * N + cc) =
                make_float2(acc[mt][nt][0], acc[mt][nt][1]);
            *(float2*)(C + (size_t)(r0 + 8) * N + cc) =
                make_float2(acc[mt][nt][2], acc[mt][nt][3]);
        }
    }
}

// ---------------------------------------------------------------------------
// RMSNorm + multimodal RoPE -> split bf16 Q,K (3-term basis, for scores)
// ---------------------------------------------------------------------------
__global__ __launch_bounds__(256) void norm_rope_kernel(
    const float* __restrict__ qkv, bf16* __restrict__ qsp, bf16* __restrict__ ksp,
    const float* __restrict__ cosT, const float* __restrict__ sinT,
    const float* __restrict__ qw, const float* __restrict__ kw)
{
    int gw = (blockIdx.x * blockDim.x + threadIdx.x) >> 5;
    int lane = threadIdx.x & 31;
    if (gw >= S_TOK * (NH + NKV)) return;
    int s = gw / (NH + NKV);
    int h = gw - s * (NH + NKV);

    const float* base; const float* w; bf16* dst;
    if (h < NH) {
        base = qkv + (size_t)s * QKVD + h * HD;               w = qw;
        dst = qsp + ((size_t)s * NH + h) * 256;
    } else {
        base = qkv + (size_t)s * QKVD + 2048 + (h - NH) * HD; w = kw;
        dst = ksp + ((size_t)s * NKV + (h - NH)) * 256;
    }

    float4 x = *(const float4*)(base + lane * 4);
    float ss = x.x * x.x + x.y * x.y + x.z * x.z + x.w * x.w;
#pragma unroll
    for (int m = 16; m > 0; m >>= 1) ss += __shfl_xor_sync(0xffffffffu, ss, m);
    float r = rsqrtf(ss * (1.0f / 128.0f) + 1e-6f);

    float4 wv = *(const float4*)(w + lane * 4);
    float xn0 = x.x * r * wv.x, xn1 = x.y * r * wv.y;
    float xn2 = x.z * r * wv.z, xn3 = x.w * r * wv.w;

    float p0 = __shfl_xor_sync(0xffffffffu, xn0, 16);
    float p1 = __shfl_xor_sync(0xffffffffu, xn1, 16);
    float p2 = __shfl_xor_sync(0xffffffffu, xn2, 16);
    float p3 = __shfl_xor_sync(0xffffffffu, xn3, 16);
    float sgn = (lane < 16) ? -1.0f : 1.0f;

    size_t toff = ((lane < 16) ? (size_t)0 : (size_t)S_TOK * HD)
                + (size_t)s * HD + lane * 4;
    float4 cv = *(const float4*)(cosT + toff);
    float4 sv = *(const float4*)(sinT + toff);

    float ov[4];
    ov[0] = xn0 * cv.x + sgn * p0 * sv.x;
    ov[1] = xn1 * cv.y + sgn * p1 * sv.y;
    ov[2] = xn2 * cv.z + sgn * p2 * sv.z;
    ov[3] = xn3 * cv.w + sgn * p3 * sv.w;

    u64 hp = 0, lp = 0;
#pragma unroll
    for (int j = 0; j < 4; j++) {
        bf16 hb = __float2bfloat16(ov[j]);
        bf16 lb = __float2bfloat16(ov[j] - __bfloat162float(hb));
        hp |= (u64)(*(unsigned short*)&hb) << (16 * j);
        lp |= (u64)(*(unsigned short*)&lb) << (16 * j);
    }
    *(u64*)(dst + lane * 4)       = hp;
    *(u64*)(dst + 128 + lane * 4) = lp;
}

// ---------------------------------------------------------------------------
// Warp-specialized flash attention (R6-proven, 256 threads: 4 S + 4 V warps).
// ---------------------------------------------------------------------------
#define AQS 0
#define AKS 32768
#define AVS 98304
#define APF 163840
#define AAF 198656
#define ALF 199168
#define ATT_SMEM 199424

__global__ __launch_bounds__(256) void attn_tc(
    const bf16* __restrict__ qs, const bf16* __restrict__ ks,
    const float* __restrict__ qkv, float* __restrict__ o)
{
    extern __shared__ char sm[];
    const u32 smb = s2u(sm);
    float* Pf = (float*)(sm + APF);
    float* Af = (float*)(sm + AAF);
    float* Lf = (float*)(sm + ALF);

    const int tid = threadIdx.x;
    const int warp = tid >> 5, lane = tid & 31;
    const bool isS = warp < 4;
    const int qt = blockIdx.x, seg = blockIdx.y, h = blockIdx.z;
    const int hkv = h >> 1;

    const bf16* Qg = qs + ((size_t)(seg * SEGLEN + qt * 64) * NH + h) * 256;
    const bf16* Kg = ks + ((size_t)(seg * SEGLEN) * NKV + hkv) * 256;
    const float* Vg = qkv + (size_t)(seg * SEGLEN) * QKVD + 3072 + hkv * HD;

#pragma unroll
    for (int j = 0; j < 8; j++) {
        int q = tid + j * 256;
        int r = q >> 5, c = q & 31;
        cp16(smb + AQS + r * 512 + ((c ^ (r & 7)) << 4),
             Qg + (size_t)r * (NH * 256) + c * 8);
    }
    cp_commit();
    if (isS) {
#pragma unroll
        for (int j = 0; j < 16; j++) {
            int q = tid + j * 128;
            int r = q >> 5, c = q & 31;
            cp16(smb + AKS + r * 512 + ((c ^ (r & 7)) << 4),
                 Kg + (size_t)r * (NKV * 256) + c * 8);
        }
        cp_commit();
    } else {
        int vt = tid - 128;
#pragma unroll
        for (int j = 0; j < 16; j++) {
            int q = vt + j * 128;
            int r = q >> 5, c = q & 31;
            cp16(smb + AVS + r * 512 + c * 16, Vg + (size_t)r * QKVD + c * 4);
        }
        cp_commit();
    }

    const int g = lane >> 2, t = lane & 3;
    float m0 = -INFINITY, m1 = -INFINITY, l0 = 0.f, l1 = 0.f;
    u64 O2[8][4];
#pragma unroll
    for (int i = 0; i < 8; i++)
#pragma unroll
        for (int j = 0; j < 4; j++) O2[i][j] = 0ULL;
    const int vt = tid - 128;
    const int tx = vt & 15, ty = vt >> 4;

    for (int it = 0; it <= 16; it++) {
        asm volatile("cp.async.wait_group 0;" ::: "memory");
        __syncthreads();

        if (isS && it < 16) {
            if (it + 1 < 16) {
                u32 kd = smb + AKS + ((it + 1) & 1) * 32768;
#pragma unroll
                for (int j = 0; j < 16; j++) {
                    int q = tid + j * 128;
                    int r = q >> 5, c = q & 31;
                    cp16(kd + r * 512 + ((c ^ (r & 7)) << 4),
                         Kg + (size_t)((it + 1) * 64 + r) * (NKV * 256) + c * 8);
                }
                cp_commit();
            }
            u32 kb = smb + AKS + (it & 1) * 32768;
            float acc[8][4];
#pragma unroll
            for (int n = 0; n < 8; n++)
#pragma unroll
                for (int c = 0; c < 4; c++) acc[n][c] = 0.f;

            const int ABASE[3] = {0, 16, 0};
            const int BBASE[3] = {0, 0, 16};
#pragma unroll
            for (int p = 0; p < 3; p++) {
#pragma unroll
                for (int k = 0; k < 8; k++) {
                    u32 afr[4], bfr[4][4];
                    int ar = warp * 16 + (lane & 15);
                    int ac = ABASE[p] + 2 * k + (lane >> 4);
                    ldsm_x4(afr, smb + AQS + ar * 512 + ((ac ^ (ar & 7)) << 4));
#pragma unroll
                    for (int pg = 0; pg < 4; pg++) {
                        int br = pg * 16 + ((lane >> 4) << 3) + (lane & 7);
                        int bc = BBASE[p] + 2 * k + ((lane >> 3) & 1);
                        ldsm_x4(bfr[pg], kb + br * 512 + ((bc ^ (br & 7)) << 4));
                    }
#pragma unroll
                    for (int nt = 0; nt < 8; nt++)
                        mma_bf16(acc[nt], afr, &bfr[nt >> 1][(nt & 1) * 2]);
                }
            }
            float mx0 = -INFINITY, mx1 = -INFINITY;
#pragma unroll
            for (int n = 0; n < 8; n++) {
#pragma unroll
                for (int c = 0; c < 4; c++) acc[n][c] *= SCALE;
                mx0 = fmaxf(mx0, fmaxf(acc[n][0], acc[n][1]));
                mx1 = fmaxf(mx1, fmaxf(acc[n][2], acc[n][3]));
            }
            mx0 = fmaxf(mx0, __shfl_xor_sync(0xffffffffu, mx0, 1));
            mx0 = fmaxf(mx0, __shfl_xor_sync(0xffffffffu, mx0, 2));
            mx1 = fmaxf(mx1, __shfl_xor_sync(0xffffffffu, mx1, 1));
            mx1 = fmaxf(mx1, __shfl_xor_sync(0xffffffffu, mx1, 2));
            float mn0 = fmaxf(m0, mx0), mn1 = fmaxf(m1, mx1);
            float a0 = __expf(m0 - mn0), a1 = __expf(m1 - mn1);
            m0 = mn0; m1 = mn1;
            float s0 = 0.f, s1 = 0.f;
#pragma unroll
            for (int n = 0; n < 8; n++) {
                acc[n][0] = __expf(acc[n][0] - mn0); s0 += acc[n][0];
                acc[n][1] = __expf(acc[n][1] - mn0); s0 += acc[n][1];
                acc[n][2] = __expf(acc[n][2] - mn1); s1 += acc[n][2];
                acc[n][3] = __expf(acc[n][3] - mn1); s1 += acc[n][3];
            }
            s0 += __shfl_xor_sync(0xffffffffu, s0, 1);
            s0 += __shfl_xor_sync(0xffffffffu, s0, 2);
            s1 += __shfl_xor_sync(0xffffffffu, s1, 1);
            s1 += __shfl_xor_sync(0xffffffffu, s1, 2);
            l0 = l0 * a0 + s0;
            l1 = l1 * a1 + s1;

            int r0 = warp * 16 + g, r1 = r0 + 8;
            float* Pb = Pf + (it & 1) * (64 * 68);
#pragma unroll
            for (int n = 0; n < 8; n++) {
                *(float2*)&Pb[r0 * 68 + n * 8 + t * 2] = make_float2(acc[n][0], acc[n][1]);
                *(float2*)&Pb[r1 * 68 + n * 8 + t * 2] = make_float2(acc[n][2], acc[n][3]);
            }
            if (t == 0) {
                Af[(it & 1) * 64 + r0] = a0;
                Af[(it & 1) * 64 + r1] = a1;
                if (it == 15) { Lf[r0] = l0; Lf[r1] = l1; }
            }
        }

        if (!isS && it > 0) {
            int j = it - 1;
            if (it < 16) {
                u32 vd = smb + AVS + (it & 1) * 32768;
#pragma unroll
                for (int jj = 0; jj < 16; jj++) {
                    int q = vt + jj * 128;
                    int r = q >> 5, c = q & 31;
                    cp16(vd + r * 512 + c * 16,
                         Vg + (size_t)(it * 64 + r) * QKVD + c * 4);
                }
                cp_commit();
            }
            const float* Pb = Pf + (j & 1) * (64 * 68);
            const char* Vb = sm + AVS + (j & 1) * 32768;
#pragma unroll
            for (int ii = 0; ii < 8; ii++) {
                float a = Af[(j & 1) * 64 + ty * 8 + ii];
                u64 ad = pack2(a, a);
#pragma unroll
                for (int c = 0; c < 4; c++) O2[ii][c] = mul2(O2[ii][c], ad);
            }
#pragma unroll 2
            for (int j4 = 0; j4 < 16; j4++) {
                float pv[8][4];
#pragma unroll
                for (int ii = 0; ii < 8; ii++) {
                    float4 tmp = *(const float4*)&Pb[(ty * 8 + ii) * 68 + j4 * 4];
                    pv[ii][0] = tmp.x; pv[ii][1] = tmp.y;
                    pv[ii][2] = tmp.z; pv[ii][3] = tmp.w;
                }
#pragma unroll
                for (int e = 0; e < 4; e++) {
                    const u64* vr = (const u64*)(Vb + ((j4 * 4 + e) * 128 + tx * 8) * 4);
                    u64 v0 = vr[0], v1 = vr[1], v2 = vr[2], v3 = vr[3];
#pragma unroll
                    for (int ii = 0; ii < 8; ii++) {
                        u64 pd = pack2(pv[ii][e], pv[ii][e]);
                        fma2(O2[ii][0], pd, v0);
                        fma2(O2[ii][1], pd, v1);
                        fma2(O2[ii][2], pd, v2);
                        fma2(O2[ii][3], pd, v3);
                    }
                }
            }
        }
    }

    if (!isS) {
#pragma unroll
        for (int ii = 0; ii < 8; ii++) {
            int row = ty * 8 + ii;
            float inv = 1.0f / Lf[row];
            float ov[8];
#pragma unroll
            for (int c = 0; c < 4; c++) {
                float lo, hi; unpack2(O2[ii][c], lo, hi);
                ov[2 * c] = lo * inv; ov[2 * c + 1] = hi * inv;
            }
            float* op = o + (size_t)(seg * SEGLEN + qt * 64 + row) * OD + h * HD + tx * 8;
            *(float4*)op       = make_float4(ov[0], ov[1], ov[2], ov[3]);
            *(float4*)(op + 4) = make_float4(ov[4], ov[5], ov[6], ov[7]);
        }
    }
}

// ---------------------------------------------------------------------------
extern "C" void kernel_launch(void* const* d_in, const int* in_sizes, int n_in,
                              void* d_out, int out_size)
{
    const float* x    = (const float*)d_in[0];
    const float* cosT = (const float*)d_in[2];
    const float* sinT = (const float*)d_in[3];
    const float* Wq   = (const float*)d_in[4];
    const float* Wk   = (const float*)d_in[5];
    const float* Wv   = (const float*)d_in[6];
    const float* Wo   = (const float*)d_in[7];
    const float* qw   = (const float*)d_in[8];
    const float* kw   = (const float*)d_in[9];
    float* out = (float*)d_out;

    f16 *x2, *w2, *o2, *wo2;
    bf16 *qsp, *ksp;
    float *qkv, *op;
    cudaGetSymbolAddress((void**)&x2,  g_x2);
    cudaGetSymbolAddress((void**)&w2,  g_w2);
    cudaGetSymbolAddress((void**)&qkv, g_qkv);
    cudaGetSymbolAddress((void**)&op,  g_o);
    cudaGetSymbolAddress((void**)&o2,  g_o2);
    cudaGetSymbolAddress((void**)&wo2, g_wo2);
    cudaGetSymbolAddress((void**)&qsp, g_qs);
    cudaGetSymbolAddress((void**)&ksp, g_ks);

    cudaFuncSetAttribute(gemm_mma,
        cudaFuncAttributeMaxDynamicSharedMemorySize, GEMM_SMEM);
    cudaFuncSetAttribute(attn_tc,
        cudaFuncAttributeMaxDynamicSharedMemorySize, ATT_SMEM);

    // launches 0-4: conversions (launch 5 = QKV gemm for ncu -s 5)
    {
        int t4 = S_TOK * HID / 4;
        cvt_split<<<(t4 + 255) / 256, 256>>>(x, x2, HID, 0, t4);
        t4 = 2048 * HID / 4;
        cvt_split<<<(t4 + 255) / 256, 256>>>(Wq, w2, HID, 1, t4);
        t4 = 1024 * HID / 4;
        cvt_split<<<(t4 + 255) / 256, 256>>>(Wk, w2 + (size_t)2048 * KP1, HID, 1, t4);
        cvt_split<<<(t4 + 255) / 256, 256>>>(Wv, w2 + (size_t)3072 * KP1, HID, 1, t4);
        t4 = HID * OD / 4;
        cvt_split<<<(t4 + 255) / 256, 256>>>(Wo, wo2, OD, 1, t4);
    }

    // QKV projection (fp16 2-term)
    gemm_mma<<<dim3(QKVD / 128, S_TOK / 128), 256, GEMM_SMEM>>>(x2, w2, qkv, QKVD, KP1);

    // RMSNorm + RoPE -> split bf16 Q,K
    int warps = S_TOK * (NH + NKV);
    norm_rope_kernel<<<(warps * 32 + 255) / 256, 256>>>(qkv, qsp, ksp, cosT, sinT, qw, kw);

    // warp-specialized attention (R6 config)
    attn_tc<<<dim3(16, 8, 16), 256, ATT_SMEM>>>(qsp, ksp, qkv, op);

    // output projection (fp16 2-term)
    {
        int t4 = S_TOK * OD / 4;
        cvt_split<<<(t4 + 255) / 256, 256>>>(op, o2, OD, 0, t4);
    }
    gemm_mma<<<dim3(HID / 128, S_TOK / 128), 256, GEMM_SMEM>>>(o2, wo2, out, HID, KP2);
}

// round 10
// speedup vs baseline: 1.3811x; 1.0095x over previous
#include <cuda_runtime.h>
#include <cuda_bf16.h>
#include <cuda_fp16.h>
#include <math.h>
#include <cstdint>

#define S_TOK  8192
#define HID    1024
#define NH     16
#define NKV    8
#define HD     128
#define SEGLEN 1024
#define QKVD   4096            // combined q|k|v output row
#define OD     2048            // attention output row
#define KP1    2048            // 2*1024 split-K (QKV proj, fp16 2-term)
#define KP2    4096            // 2*2048 split-K (out proj, fp16 2-term)
#define SCALE  0.08838834764831845f

typedef unsigned long long u64;
typedef unsigned int u32;
typedef __nv_bfloat16 bf16;
typedef __half f16;

// ---------------- scratch (static device arrays, no runtime alloc) ----------
__device__ f16   g_x2 [S_TOK * KP1];      // x split fp16 [8192,2048]  hi|lo
__device__ f16   g_w2 [QKVD  * KP1];      // Wqkv split   [4096,2048]  hi|hi
__device__ bf16  g_qs [S_TOK * NH  * 256];// Q split bf16 [S][16][hi128|lo128]
__device__ bf16  g_ks [S_TOK * NKV * 256];// K split bf16 [S][8][hi128|lo128]
__device__ float g_v  [S_TOK * NKV * HD]; // V fp32 packed [S][8][128]
__device__ f16   g_o2 [S_TOK * KP2];      // attn out split [8192,4096] hi|lo
__device__ f16   g_wo2[HID   * KP2];      // Wo split [1024,4096] hi|hi

// ---------------- small helpers --------------------------------------------
__device__ __forceinline__ u64 pack2(float a, float b) {
    u64 r; asm("mov.b64 %0,{%1,%2};" : "=l"(r) : "f"(a), "f"(b)); return r;
}
__device__ __forceinline__ void unpack2(u64 v, float& a, float& b) {
    asm("mov.b64 {%0,%1},%2;" : "=f"(a), "=f"(b) : "l"(v));
}
__device__ __forceinline__ void fma2(u64& c, u64 a, u64 b) {
    asm("fma.rn.f32x2 %0,%1,%2,%3;" : "=l"(c) : "l"(a), "l"(b), "l"(c));
}
__device__ __forceinline__ u64 mul2(u64 a, u64 b) {
    u64 r; asm("mul.rn.f32x2 %0,%1,%2;" : "=l"(r) : "l"(a), "l"(b)); return r;
}
__device__ __forceinline__ u32 s2u(const void* p) {
    u32 a; asm("{ .reg .u64 t; cvta.to.shared.u64 t,%1; cvt.u32.u64 %0,t; }"
               : "=r"(a) : "l"(p));
    return a;
}
__device__ __forceinline__ void cp16(u32 dst, const void* src) {
    asm volatile("cp.async.cg.shared.global [%0],[%1],16;" :: "r"(dst), "l"(src));
}
__device__ __forceinline__ void cp_commit() {
    asm volatile("cp.async.commit_group;" ::: "memory");
}
__device__ __forceinline__ void ldsm_x4(u32* r, u32 addr) {
    asm volatile("ldmatrix.sync.aligned.m8n8.x4.shared.b16 {%0,%1,%2,%3},[%4];"
                 : "=r"(r[0]), "=r"(r[1]), "=r"(r[2]), "=r"(r[3]) : "r"(addr));
}
__device__ __forceinline__ void mma_bf16(float* d, const u32* a, const u32* b) {
    asm volatile(
        "mma.sync.aligned.m16n8k16.row.col.f32.bf16.bf16.f32 "
        "{%0,%1,%2,%3},{%4,%5,%6,%7},{%8,%9},{%0,%1,%2,%3};"
        : "+f"(d[0]), "+f"(d[1]), "+f"(d[2]), "+f"(d[3])
        : "r"(a[0]), "r"(a[1]), "r"(a[2]), "r"(a[3]), "r"(b[0]), "r"(b[1]));
}
__device__ __forceinline__ void mma_f16(float* d, const u32* a, const u32* b) {
    asm volatile(
        "mma.sync.aligned.m16n8k16.row.col.f32.f16.f16.f32 "
        "{%0,%1,%2,%3},{%4,%5,%6,%7},{%8,%9},{%0,%1,%2,%3};"
        : "+f"(d[0]), "+f"(d[1]), "+f"(d[2]), "+f"(d[3])
        : "r"(a[0]), "r"(a[1]), "r"(a[2]), "r"(a[3]), "r"(b[0]), "r"(b[1]));
}
__device__ __forceinline__ u32 packh2(float a, float b) {
    f16 h0 = __float2half(a), h1 = __float2half(b);
    return (u32)(*(unsigned short*)&h0) | ((u32)(*(unsigned short*)&h1) << 16);
}

// ---------------------------------------------------------------------------
// fp16 2-term split: src fp32 [M,K] -> dst f16 [M,2K]
//   A side (isB=0): [ hi | lo ],  B side (isB=1): [ hi | hi ]
// ---------------------------------------------------------------------------
__global__ __launch_bounds__(256) void cvt_split(
    const float* __restrict__ src, f16* __restrict__ dst,
    int K, int isB, int total4)
{
    int i = blockIdx.x * blockDim.x + threadIdx.x;
    if (i >= total4) return;
    int perRow = K >> 2;
    int row = i / perRow;
    int c4 = (i - row * perRow) << 2;
    float4 v = *(const float4*)(src + (size_t)row * K + c4);
    float f[4] = {v.x, v.y, v.z, v.w};
    u64 hp = 0, lp = 0;
#pragma unroll
    for (int j = 0; j < 4; j++) {
        f16 hb = __float2half(f[j]);
        f16 lb = __float2half(f[j] - __half2float(hb));
        hp |= (u64)(*(unsigned short*)&hb) << (16 * j);
        lp |= (u64)(*(unsigned short*)&lb) << (16 * j);
    }
    f16* d = dst + (size_t)row * (2 * K) + c4;
    *(u64*)d       = hp;
    *(u64*)(d + K) = isB ? hp : lp;
}

// ---------------------------------------------------------------------------
// mma.sync GEMM (R4/R9-proven mainloop): C = A[M,Kp] f16 @ B[N,Kp]^T f16
// CTA 128x128, 8 warps (2Mx4N), BK=64, 3-stage cp.async.
// fuse==0: plain fp32 store to C (out-proj)
// fuse==1: QKV epilogue — q/k col-blocks get fused RMSNorm+RoPE -> split bf16;
//          v col-blocks stored packed fp32 to vout.
// ---------------------------------------------------------------------------
#define GSTAGE 32768
#define GEMM_SMEM (3 * GSTAGE)   // 98304

__global__ __launch_bounds__(256) void gemm_mma(
    const f16* __restrict__ A, const f16* __restrict__ B,
    float* __restrict__ C, int N, int Kp, int fuse,
    bf16* __restrict__ qs, bf16* __restrict__ ks, float* __restrict__ vout,
    const float* __restrict__ cosT, const float* __restrict__ sinT,
    const float* __restrict__ qw, const float* __restrict__ kw)
{
    extern __shared__ char smc[];
    const u32 smb = s2u(smc);
    const int tid = threadIdx.x;
    const int warp = tid >> 5, lane = tid & 31;
    const int wM = warp >> 2, wN = warp & 3;
    const int m0 = blockIdx.y << 7, n0 = blockIdx.x << 7;
    const int chunks = Kp >> 6;

    const f16* Ag = A + (size_t)m0 * Kp;
    const f16* Bg = B + (size_t)n0 * Kp;

    float acc[4][4][4];
#pragma unroll
    for (int a = 0; a < 4; a++)
#pragma unroll
        for (int b = 0; b < 4; b++)
#pragma unroll
            for (int c = 0; c < 4; c++) acc[a][b][c] = 0.f;

    auto load_stage = [&](int st, int ch) {
        u32 sa = smb + st * GSTAGE;
        u32 sb = sa + 16384;
#pragma unroll
        for (int j = 0; j < 4; j++) {
            int q = tid + j * 256;
            int r = q >> 3, c = q & 7;
            cp16(sa + r * 128 + ((c ^ (r & 7)) << 4),
                 Ag + (size_t)r * Kp + ch * 64 + c * 8);
        }
#pragma unroll
        for (int j = 0; j < 4; j++) {
            int q = tid + j * 256;
            int r = q >> 3, c = q & 7;
            cp16(sb + r * 128 + ((c ^ (r & 7)) << 4),
                 Bg + (size_t)r * Kp + ch * 64 + c * 8);
        }
        cp_commit();
    };

    load_stage(0, 0);
    load_stage(1, 1);

    for (int i = 0; i < chunks; i++) {
        int s = i % 3;
        asm volatile("cp.async.wait_group 1;" ::: "memory");
        __syncthreads();
        if (i + 2 < chunks) load_stage((i + 2) % 3, i + 2);
        else cp_commit();

        u32 sa = smb + s * GSTAGE;
        u32 sb = sa + 16384;
#pragma unroll
        for (int kk = 0; kk < 4; kk++) {
            u32 afr[4][4], bfr[2][4];
#pragma unroll
            for (int mt = 0; mt < 4; mt++) {
                int row = wM * 64 + mt * 16 + (lane & 15);
                int ch = kk * 2 + (lane >> 4);
                ldsm_x4(afr[mt], sa + row * 128 + ((ch ^ (row & 7)) << 4));
            }
#pragma unroll
            for (int p = 0; p < 2; p++) {
                int row = wN * 32 + p * 16 + ((lane >> 4) << 3) + (lane & 7);
                int ch = kk * 2 + ((lane >> 3) & 1);
                ldsm_x4(bfr[p], sb + row * 128 + ((ch ^ (row & 7)) << 4));
            }
#pragma unroll
            for (int mt = 0; mt < 4; mt++)
#pragma unroll
                for (int nt = 0; nt < 4; nt++)
                    mma_f16(acc[mt][nt], afr[mt], &bfr[nt >> 1][(nt & 1) * 2]);
        }
    }

    const int g = lane >> 2, t = lane & 3;

    if (!fuse) {
        // plain fp32 epilogue (out projection)
#pragma unroll
        for (int mt = 0; mt < 4; mt++) {
            int r0 = m0 + wM * 64 + mt * 16 + g;
#pragma unroll
            for (int nt = 0; nt < 4; nt++) {
                int cc = n0 + wN * 32 + nt * 8 + t * 2;
                *(float2*)(C + (size_t)r0 * N + cc) =
                    make_float2(acc[mt][nt][0], acc[mt][nt][1]);
                *(float2*)(C + (size_t)(r0 + 8) * N + cc) =
                    make_float2(acc[mt][nt][2], acc[mt][nt][3]);
            }
        }
        return;
    }

    const int nb = blockIdx.x;   // 0..15 q-heads, 16..23 k-heads, 24..31 v-heads
    if (nb >= 24) {
        // V block: packed fp32 store [s][8][128]
        int vc0 = (nb - 24) * 128;
#pragma unroll
        for (int mt = 0; mt < 4; mt++) {
            int r0 = m0 + wM * 64 + mt * 16 + g;
#pragma unroll
            for (int nt = 0; nt < 4; nt++) {
                int cc = vc0 + wN * 32 + nt * 8 + t * 2;
                *(float2*)(vout + (size_t)r0 * (NKV * HD) + cc) =
                    make_float2(acc[mt][nt][0], acc[mt][nt][1]);
                *(float2*)(vout + (size_t)(r0 + 8) * (NKV * HD) + cc) =
                    make_float2(acc[mt][nt][2], acc[mt][nt][3]);
            }
        }
        return;
    }

    // q/k block: stage tile to smem, then fused RMSNorm + RoPE per token row
    float* Cs = (float*)smc;                    // [128][132]
    __syncthreads();                            // mainloop smem reads done
#pragma unroll
    for (int mt = 0; mt < 4; mt++) {
        int rl = wM * 64 + mt * 16 + g;
#pragma unroll
        for (int nt = 0; nt < 4; nt++) {
            int cl = wN * 32 + nt * 8 + t * 2;
            *(float2*)&Cs[rl * 132 + cl]       = make_float2(acc[mt][nt][0], acc[mt][nt][1]);
            *(float2*)&Cs[(rl + 8) * 132 + cl] = make_float2(acc[mt][nt][2], acc[mt][nt][3]);
        }
    }
    __syncthreads();

    const bool isQ = (nb < 16);
    const float* w = isQ ? qw : kw;
    const float4 wv = *(const float4*)(w + lane * 4);
    const float sgn = (lane < 16) ? -1.0f : 1.0f;
    const size_t tstream = (lane < 16) ? (size_t)0 : (size_t)S_TOK * HD;

#pragma unroll 4
    for (int rr = 0; rr < 16; rr++) {
        int row = warp * 16 + rr;
        int s = m0 + row;

        float4 x = *(const float4*)&Cs[row * 132 + lane * 4];
        float ss = x.x * x.x + x.y * x.y + x.z * x.z + x.w * x.w;
#pragma unroll
        for (int m = 16; m > 0; m >>= 1) ss += __shfl_xor_sync(0xffffffffu, ss, m);
        float r = rsqrtf(ss * (1.0f / 128.0f) + 1e-6f);

        float xn0 = x.x * r * wv.x, xn1 = x.y * r * wv.y;
        float xn2 = x.z * r * wv.z, xn3 = x.w * r * wv.w;

        float p0 = __shfl_xor_sync(0xffffffffu, xn0, 16);
        float p1 = __shfl_xor_sync(0xffffffffu, xn1, 16);
        float p2 = __shfl_xor_sync(0xffffffffu, xn2, 16);
        float p3 = __shfl_xor_sync(0xffffffffu, xn3, 16);

        size_t toff = tstream + (size_t)s * HD + lane * 4;
        float4 cv = *(const float4*)(cosT + toff);
        float4 sv = *(const float4*)(sinT + toff);

        float ov[4];
        ov[0] = xn0 * cv.x + sgn * p0 * sv.x;
        ov[1] = xn1 * cv.y + sgn * p1 * sv.y;
        ov[2] = xn2 * cv.z + sgn * p2 * sv.z;
        ov[3] = xn3 * cv.w + sgn * p3 * sv.w;

        u64 hp = 0, lp = 0;
#pragma unroll
        for (int j = 0; j < 4; j++) {
            bf16 hb = __float2bfloat16(ov[j]);
            bf16 lb = __float2bfloat16(ov[j] - __bfloat162float(hb));
            hp |= (u64)(*(unsigned short*)&hb) << (16 * j);
            lp |= (u64)(*(unsigned short*)&lb) << (16 * j);
        }
        bf16* dst = isQ ? (qs + ((size_t)s * NH + nb) * 256)
                        : (ks + ((size_t)s * NKV + (nb - 16)) * 256);
        *(u64*)(dst + lane * 4)       = hp;
        *(u64*)(dst + 128 + lane * 4) = lp;
    }
}

// ---------------------------------------------------------------------------
// Warp-specialized flash attention (R6-proven core, 4 S + 4 V warps).
// V read from packed g_v (stride 1024 f32); epilogue writes split fp16 o2.
// ---------------------------------------------------------------------------
#define AQS 0
#define AKS 32768
#define AVS 98304
#define APF 163840
#define AAF 198656
#define ALF 199168
#define ATT_SMEM 199424
#define VSTR (NKV * HD)   // 1024 floats per token row

__global__ __launch_bounds__(256) void attn_tc(
    const bf16* __restrict__ qs, const bf16* __restrict__ ks,
    const float* __restrict__ v, f16* __restrict__ o2)
{
    extern __shared__ char sm[];
    const u32 smb = s2u(sm);
    float* Pf = (float*)(sm + APF);
    float* Af = (float*)(sm + AAF);
    float* Lf = (float*)(sm + ALF);

    const int tid = threadIdx.x;
    const int warp = tid >> 5, lane = tid & 31;
    const bool isS = warp < 4;
    const int qt = blockIdx.x, seg = blockIdx.y, h = blockIdx.z;
    const int hkv = h >> 1;

    const bf16* Qg = qs + ((size_t)(seg * SEGLEN + qt * 64) * NH + h) * 256;
    const bf16* Kg = ks + ((size_t)(seg * SEGLEN) * NKV + hkv) * 256;
    const float* Vg = v + (size_t)(seg * SEGLEN) * VSTR + hkv * HD;

#pragma unroll
    for (int j = 0; j < 8; j++) {
        int q = tid + j * 256;
        int r = q >> 5, c = q & 31;
        cp16(smb + AQS + r * 512 + ((c ^ (r & 7)) << 4),
             Qg + (size_t)r * (NH * 256) + c * 8);
    }
    cp_commit();
    if (isS) {
#pragma unroll
        for (int j = 0; j < 16; j++) {
            int q = tid + j * 128;
            int r = q >> 5, c = q & 31;
            cp16(smb + AKS + r * 512 + ((c ^ (r & 7)) << 4),
                 Kg + (size_t)r * (NKV * 256) + c * 8);
        }
        cp_commit();
    } else {
        int vt = tid - 128;
#pragma unroll
        for (int j = 0; j < 16; j++) {
            int q = vt + j * 128;
            int r = q >> 5, c = q & 31;
            cp16(smb + AVS + r * 512 + c * 16, Vg + (size_t)r * VSTR + c * 4);
        }
        cp_commit();
    }

    const int g = lane >> 2, t = lane & 3;
    float m0 = -INFINITY, m1 = -INFINITY, l0 = 0.f, l1 = 0.f;
    u64 O2[8][4];
#pragma unroll
    for (int i = 0; i < 8; i++)
#pragma unroll
        for (int j = 0; j < 4; j++) O2[i][j] = 0ULL;
    const int vt = tid - 128;
    const int tx = vt & 15, ty = vt >> 4;

    for (int it = 0; it <= 16; it++) {
        asm volatile("cp.async.wait_group 0;" ::: "memory");
        __syncthreads();

        if (isS && it < 16) {
            if (it + 1 < 16) {
                u32 kd = smb + AKS + ((it + 1) & 1) * 32768;
#pragma unroll
                for (int j = 0; j < 16; j++) {
                    int q = tid + j * 128;
                    int r = q >> 5, c = q & 31;
                    cp16(kd + r * 512 + ((c ^ (r & 7)) << 4),
                         Kg + (size_t)((it + 1) * 64 + r) * (NKV * 256) + c * 8);
                }
                cp_commit();
            }
            u32 kb = smb + AKS + (it & 1) * 32768;
            float acc[8][4];
#pragma unroll
            for (int n = 0; n < 8; n++)
#pragma unroll
                for (int c = 0; c < 4; c++) acc[n][c] = 0.f;

            const int ABASE[3] = {0, 16, 0};
            const int BBASE[3] = {0, 0, 16};
#pragma unroll
            for (int p = 0; p < 3; p++) {
#pragma unroll
                for (int k = 0; k < 8; k++) {
                    u32 afr[4], bfr[4][4];
                    int ar = warp * 16 + (lane & 15);
                    int ac = ABASE[p] + 2 * k + (lane >> 4);
                    ldsm_x4(afr, smb + AQS + ar * 512 + ((ac ^ (ar & 7)) << 4));
#pragma unroll
                    for (int pg = 0; pg < 4; pg++) {
                        int br = pg * 16 + ((lane >> 4) << 3) + (lane & 7);
                        int bc = BBASE[p] + 2 * k + ((lane >> 3) & 1);
                        ldsm_x4(bfr[pg], kb + br * 512 + ((bc ^ (br & 7)) << 4));
                    }
#pragma unroll
                    for (int nt = 0; nt < 8; nt++)
                        mma_bf16(acc[nt], afr, &bfr[nt >> 1][(nt & 1) * 2]);
                }
            }
            float mx0 = -INFINITY, mx1 = -INFINITY;
#pragma unroll
            for (int n = 0; n < 8; n++) {
#pragma unroll
                for (int c = 0; c < 4; c++) acc[n][c] *= SCALE;
                mx0 = fmaxf(mx0, fmaxf(acc[n][0], acc[n][1]));
                mx1 = fmaxf(mx1, fmaxf(acc[n][2], acc[n][3]));
            }
            mx0 = fmaxf(mx0, __shfl_xor_sync(0xffffffffu, mx0, 1));
            mx0 = fmaxf(mx0, __shfl_xor_sync(0xffffffffu, mx0, 2));
            mx1 = fmaxf(mx1, __shfl_xor_sync(0xffffffffu, mx1, 1));
            mx1 = fmaxf(mx1, __shfl_xor_sync(0xffffffffu, mx1, 2));
            float mn0 = fmaxf(m0, mx0), mn1 = fmaxf(m1, mx1);
            float a0 = __expf(m0 - mn0), a1 = __expf(m1 - mn1);
            m0 = mn0; m1 = mn1;
            float s0 = 0.f, s1 = 0.f;
#pragma unroll
            for (int n = 0; n < 8; n++) {
                acc[n][0] = __expf(acc[n][0] - mn0); s0 += acc[n][0];
                acc[n][1] = __expf(acc[n][1] - mn0); s0 += acc[n][1];
                acc[n][2] = __expf(acc[n][2] - mn1); s1 += acc[n][2];
                acc[n][3] = __expf(acc[n][3] - mn1); s1 += acc[n][3];
            }
            s0 += __shfl_xor_sync(0xffffffffu, s0, 1);
            s0 += __shfl_xor_sync(0xffffffffu, s0, 2);
            s1 += __shfl_xor_sync(0xffffffffu, s1, 1);
            s1 += __shfl_xor_sync(0xffffffffu, s1, 2);
            l0 = l0 * a0 + s0;
            l1 = l1 * a1 + s1;

            int r0 = warp * 16 + g, r1 = r0 + 8;
            float* Pb = Pf + (it & 1) * (64 * 68);
#pragma unroll
            for (int n = 0; n < 8; n++) {
                *(float2*)&Pb[r0 * 68 + n * 8 + t * 2] = make_float2(acc[n][0], acc[n][1]);
                *(float2*)&Pb[r1 * 68 + n * 8 + t * 2] = make_float2(acc[n][2], acc[n][3]);
            }
            if (t == 0) {
                Af[(it & 1) * 64 + r0] = a0;
                Af[(it & 1) * 64 + r1] = a1;
                if (it == 15) { Lf[r0] = l0; Lf[r1] = l1; }
            }
        }

        if (!isS && it > 0) {
            int j = it - 1;
            if (it < 16) {
                u32 vd = smb + AVS + (it & 1) * 32768;
#pragma unroll
                for (int jj = 0; jj < 16; jj++) {
                    int q = vt + jj * 128;
                    int r = q >> 5, c = q & 31;
                    cp16(vd + r * 512 + c * 16,
                         Vg + (size_t)(it * 64 + r) * VSTR + c * 4);
                }
                cp_commit();
            }
            const float* Pb = Pf + (j & 1) * (64 * 68);
            const char* Vb = sm + AVS + (j & 1) * 32768;
#pragma unroll
            for (int ii = 0; ii < 8; ii++) {
                float a = Af[(j & 1) * 64 + ty * 8 + ii];
                u64 ad = pack2(a, a);
#pragma unroll
                for (int c = 0; c < 4; c++) O2[ii][c] = mul2(O2[ii][c], ad);
            }
#pragma unroll 2
            for (int j4 = 0; j4 < 16; j4++) {
                float pv[8][4];
#pragma unroll
                for (int ii = 0; ii < 8; ii++) {
                    float4 tmp = *(const float4*)&Pb[(ty * 8 + ii) * 68 + j4 * 4];
                    pv[ii][0] = tmp.x; pv[ii][1] = tmp.y;
                    pv[ii][2] = tmp.z; pv[ii][3] = tmp.w;
                }
#pragma unroll
                for (int e = 0; e < 4; e++) {
                    const u64* vr = (const u64*)(Vb + ((j4 * 4 + e) * 128 + tx * 8) * 4);
                    u64 v0 = vr[0], v1 = vr[1], v2 = vr[2], v3 = vr[3];
#pragma unroll
                    for (int ii = 0; ii < 8; ii++) {
                        u64 pd = pack2(pv[ii][e], pv[ii][e]);
                        fma2(O2[ii][0], pd, v0);
                        fma2(O2[ii][1], pd, v1);
                        fma2(O2[ii][2], pd, v2);
                        fma2(O2[ii][3], pd, v3);
                    }
                }
            }
        }
    }

    // epilogue: normalize + fp16 2-term split, direct to o2 [hi(2048)|lo(2048)]
    if (!isS) {
#pragma unroll
        for (int ii = 0; ii < 8; ii++) {
            int row = ty * 8 + ii;
            float inv = 1.0f / Lf[row];
            float ov[8];
#pragma unroll
            for (int c = 0; c < 4; c++) {
                float lo, hi; unpack2(O2[ii][c], lo, hi);
                ov[2 * c] = lo * inv; ov[2 * c + 1] = hi * inv;
            }
            u32 hw[4], lw[4];
#pragma unroll
            for (int m = 0; m < 4; m++) {
                float a0 = ov[2 * m], a1 = ov[2 * m + 1];
                f16 h0 = __float2half(a0), h1 = __float2half(a1);
                hw[m] = (u32)(*(unsigned short*)&h0) | ((u32)(*(unsigned short*)&h1) << 16);
                float r0f = a0 - __half2float(h0), r1f = a1 - __half2float(h1);
                lw[m] = packh2(r0f, r1f);
            }
            f16* orow = o2 + (size_t)(seg * SEGLEN + qt * 64 + row) * KP2 + h * HD + tx * 8;
            *(uint4*)orow          = make_uint4(hw[0], hw[1], hw[2], hw[3]);
            *(uint4*)(orow + OD)   = make_uint4(lw[0], lw[1], lw[2], lw[3]);
        }
    }
}

// ---------------------------------------------------------------------------
extern "C" void kernel_launch(void* const* d_in, const int* in_sizes, int n_in,
                              void* d_out, int out_size)
{
    const float* x    = (const float*)d_in[0];
    const float* cosT = (const float*)d_in[2];
    const float* sinT = (const float*)d_in[3];
    const float* Wq   = (const float*)d_in[4];
    const float* Wk   = (const float*)d_in[5];
    const float* Wv   = (const float*)d_in[6];
    const float* Wo   = (const float*)d_in[7];
    const float* qw   = (const float*)d_in[8];
    const float* kw   = (const float*)d_in[9];
    float* out = (float*)d_out;

    f16 *x2, *w2, *o2, *wo2;
    bf16 *qsp, *ksp;
    float *vp;
    cudaGetSymbolAddress((void**)&x2,  g_x2);
    cudaGetSymbolAddress((void**)&w2,  g_w2);
    cudaGetSymbolAddress((void**)&o2,  g_o2);
    cudaGetSymbolAddress((void**)&wo2, g_wo2);
    cudaGetSymbolAddress((void**)&qsp, g_qs);
    cudaGetSymbolAddress((void**)&ksp, g_ks);
    cudaGetSymbolAddress((void**)&vp,  g_v);

    cudaFuncSetAttribute(gemm_mma,
        cudaFuncAttributeMaxDynamicSharedMemorySize, GEMM_SMEM);
    cudaFuncSetAttribute(attn_tc,
        cudaFuncAttributeMaxDynamicSharedMemorySize, ATT_SMEM);

    // launches 0-4: conversions (launch 5 = QKV gemm for ncu -s 5)
    {
        int t4 = S_TOK * HID / 4;
        cvt_split<<<(t4 + 255) / 256, 256>>>(x, x2, HID, 0, t4);
        t4 = 2048 * HID / 4;
        cvt_split<<<(t4 + 255) / 256, 256>>>(Wq, w2, HID, 1, t4);
        t4 = 1024 * HID / 4;
        cvt_split<<<(t4 + 255) / 256, 256>>>(Wk, w2 + (size_t)2048 * KP1, HID, 1, t4);
        cvt_split<<<(t4 + 255) / 256, 256>>>(Wv, w2 + (size_t)3072 * KP1, HID, 1, t4);
        t4 = HID * OD / 4;
        cvt_split<<<(t4 + 255) / 256, 256>>>(Wo, wo2, OD, 1, t4);
    }

    // QKV projection with fused RMSNorm+RoPE epilogue
    gemm_mma<<<dim3(QKVD / 128, S_TOK / 128), 256, GEMM_SMEM>>>(
        x2, w2, nullptr, QKVD, KP1, 1, qsp, ksp, vp, cosT, sinT, qw, kw);

    // warp-specialized attention (writes split fp16 o2 directly)
    attn_tc<<<dim3(16, 8, 16), 256, ATT_SMEM>>>(qsp, ksp, vp, o2);

    // output projection (plain epilogue -> d_out)
    gemm_mma<<<dim3(HID / 128, S_TOK / 128), 256, GEMM_SMEM>>>(
        o2, wo2, out, HID, KP2, 0, nullptr, nullptr, nullptr,
        nullptr, nullptr, nullptr, nullptr);
}

// round 11
// speedup vs baseline: 1.5164x; 1.0980x over previous
#include <cuda_runtime.h>
#include <cuda_bf16.h>
#include <cuda_fp16.h>
#include <math.h>
#include <cstdint>

#define S_TOK  8192
#define HID    1024
#define NH     16
#define NKV    8
#define HD     128
#define SEGLEN 1024
#define QKVD   4096
#define OD     2048
#define KP1    2048            // 2*1024 split-K (QKV proj, fp16 2-term)
#define KP2    4096            // 2*2048 split-K (out proj, fp16 2-term)
#define SCALE  0.08838834764831845f

typedef unsigned long long u64;
typedef unsigned int u32;
typedef __nv_bfloat16 bf16;
typedef __half f16;

// ---------------- scratch -----------------------------------------------
__device__ f16   g_x2 [S_TOK * KP1];      // x split fp16 [8192,2048]  hi|lo
__device__ f16   g_w2 [QKVD  * KP1];      // Wqkv split   [4096,2048]  hi|hi
__device__ bf16  g_qs [S_TOK * NH  * 256];// Q split bf16 [S][16][hi128|lo128]
__device__ bf16  g_ks [S_TOK * NKV * 256];// K split bf16 [S][8][hi128|lo128]
__device__ float g_v  [S_TOK * NKV * HD]; // V fp32 packed [S][8][128]
__device__ f16   g_vh [S_TOK * NKV * 32]; // V cols 96..127 fp16 [S][8][32]
__device__ f16   g_o2 [S_TOK * KP2];      // attn out split [8192,4096] hi|lo
__device__ f16   g_wo2[HID   * KP2];      // Wo split [1024,4096] hi|hi

// ---------------- helpers ------------------------------------------------
__device__ __forceinline__ u64 pack2(float a, float b) {
    u64 r; asm("mov.b64 %0,{%1,%2};" : "=l"(r) : "f"(a), "f"(b)); return r;
}
__device__ __forceinline__ void unpack2(u64 v, float& a, float& b) {
    asm("mov.b64 {%0,%1},%2;" : "=f"(a), "=f"(b) : "l"(v));
}
__device__ __forceinline__ void fma2(u64& c, u64 a, u64 b) {
    asm("fma.rn.f32x2 %0,%1,%2,%3;" : "=l"(c) : "l"(a), "l"(b), "l"(c));
}
__device__ __forceinline__ u64 mul2(u64 a, u64 b) {
    u64 r; asm("mul.rn.f32x2 %0,%1,%2;" : "=l"(r) : "l"(a), "l"(b)); return r;
}
__device__ __forceinline__ u32 s2u(const void* p) {
    u32 a; asm("{ .reg .u64 t; cvta.to.shared.u64 t,%1; cvt.u32.u64 %0,t; }"
               : "=r"(a) : "l"(p));
    return a;
}
__device__ __forceinline__ void cp16(u32 dst, const void* src) {
    asm volatile("cp.async.cg.shared.global [%0],[%1],16;" :: "r"(dst), "l"(src));
}
__device__ __forceinline__ void cp_commit() {
    asm volatile("cp.async.commit_group;" ::: "memory");
}
__device__ __forceinline__ void ldsm_x4(u32* r, u32 addr) {
    asm volatile("ldmatrix.sync.aligned.m8n8.x4.shared.b16 {%0,%1,%2,%3},[%4];"
                 : "=r"(r[0]), "=r"(r[1]), "=r"(r[2]), "=r"(r[3]) : "r"(addr));
}
__device__ __forceinline__ void ldsm_x4_t(u32* r, u32 addr) {
    asm volatile("ldmatrix.sync.aligned.m8n8.x4.trans.shared.b16 {%0,%1,%2,%3},[%4];"
                 : "=r"(r[0]), "=r"(r[1]), "=r"(r[2]), "=r"(r[3]) : "r"(addr));
}
__device__ __forceinline__ void mma_bf16(float* d, const u32* a, const u32* b) {
    asm volatile(
        "mma.sync.aligned.m16n8k16.row.col.f32.bf16.bf16.f32 "
        "{%0,%1,%2,%3},{%4,%5,%6,%7},{%8,%9},{%0,%1,%2,%3};"
        : "+f"(d[0]), "+f"(d[1]), "+f"(d[2]), "+f"(d[3])
        : "r"(a[0]), "r"(a[1]), "r"(a[2]), "r"(a[3]), "r"(b[0]), "r"(b[1]));
}
__device__ __forceinline__ void mma_f16(float* d, const u32* a, const u32* b) {
    asm volatile(
        "mma.sync.aligned.m16n8k16.row.col.f32.f16.f16.f32 "
        "{%0,%1,%2,%3},{%4,%5,%6,%7},{%8,%9},{%0,%1,%2,%3};"
        : "+f"(d[0]), "+f"(d[1]), "+f"(d[2]), "+f"(d[3])
        : "r"(a[0]), "r"(a[1]), "r"(a[2]), "r"(a[3]), "r"(b[0]), "r"(b[1]));
}
// pack two floats -> u32 {low f16 = a, high f16 = b}
__device__ __forceinline__ u32 packh2(float a, float b) {
    u32 r; asm("cvt.rn.f16x2.f32 %0,%1,%2;" : "=r"(r) : "f"(b), "f"(a));
    return r;
}

// ---------------------------------------------------------------------------
// fp16 2-term split: src fp32 [M,K] -> dst f16 [M,2K]
//   A side (isB=0): [ hi | lo ],  B side (isB=1): [ hi | hi ]
// ---------------------------------------------------------------------------
__global__ __launch_bounds__(256) void cvt_split(
    const float* __restrict__ src, f16* __restrict__ dst,
    int K, int isB, int total4)
{
    int i = blockIdx.x * blockDim.x + threadIdx.x;
    if (i >= total4) return;
    int perRow = K >> 2;
    int row = i / perRow;
    int c4 = (i - row * perRow) << 2;
    float4 v = *(const float4*)(src + (size_t)row * K + c4);
    float f[4] = {v.x, v.y, v.z, v.w};
    u64 hp = 0, lp = 0;
#pragma unroll
    for (int j = 0; j < 4; j++) {
        f16 hb = __float2half(f[j]);
        f16 lb = __float2half(f[j] - __half2float(hb));
        hp |= (u64)(*(unsigned short*)&hb) << (16 * j);
        lp |= (u64)(*(unsigned short*)&lb) << (16 * j);
    }
    f16* d = dst + (size_t)row * (2 * K) + c4;
    *(u64*)d       = hp;
    *(u64*)(d + K) = isB ? hp : lp;
}

// ---------------------------------------------------------------------------
// mma.sync GEMM (R9/R10-proven mainloop): C = A[M,Kp] f16 @ B[N,Kp]^T f16
// fuse==0: plain fp32 epilogue. fuse==1: QKV epilogue (norm+rope / V stores).
// ---------------------------------------------------------------------------
#define GSTAGE 32768
#define GEMM_SMEM (3 * GSTAGE)

__global__ __launch_bounds__(256) void gemm_mma(
    const f16* __restrict__ A, const f16* __restrict__ B,
    float* __restrict__ C, int N, int Kp, int fuse,
    bf16* __restrict__ qs, bf16* __restrict__ ks,
    float* __restrict__ vout, f16* __restrict__ vhout,
    const float* __restrict__ cosT, const float* __restrict__ sinT,
    const float* __restrict__ qw, const float* __restrict__ kw)
{
    extern __shared__ char smc[];
    const u32 smb = s2u(smc);
    const int tid = threadIdx.x;
    const int warp = tid >> 5, lane = tid & 31;
    const int wM = warp >> 2, wN = warp & 3;
    const int m0 = blockIdx.y << 7, n0 = blockIdx.x << 7;
    const int chunks = Kp >> 6;

    const f16* Ag = A + (size_t)m0 * Kp;
    const f16* Bg = B + (size_t)n0 * Kp;

    float acc[4][4][4];
#pragma unroll
    for (int a = 0; a < 4; a++)
#pragma unroll
        for (int b = 0; b < 4; b++)
#pragma unroll
            for (int c = 0; c < 4; c++) acc[a][b][c] = 0.f;

    auto load_stage = [&](int st, int ch) {
        u32 sa = smb + st * GSTAGE;
        u32 sb = sa + 16384;
#pragma unroll
        for (int j = 0; j < 4; j++) {
            int q = tid + j * 256;
            int r = q >> 3, c = q & 7;
            cp16(sa + r * 128 + ((c ^ (r & 7)) << 4),
                 Ag + (size_t)r * Kp + ch * 64 + c * 8);
        }
#pragma unroll
        for (int j = 0; j < 4; j++) {
            int q = tid + j * 256;
            int r = q >> 3, c = q & 7;
            cp16(sb + r * 128 + ((c ^ (r & 7)) << 4),
                 Bg + (size_t)r * Kp + ch * 64 + c * 8);
        }
        cp_commit();
    };

    load_stage(0, 0);
    load_stage(1, 1);

    for (int i = 0; i < chunks; i++) {
        int s = i % 3;
        asm volatile("cp.async.wait_group 1;" ::: "memory");
        __syncthreads();
        if (i + 2 < chunks) load_stage((i + 2) % 3, i + 2);
        else cp_commit();

        u32 sa = smb + s * GSTAGE;
        u32 sb = sa + 16384;
#pragma unroll
        for (int kk = 0; kk < 4; kk++) {
            u32 afr[4][4], bfr[2][4];
#pragma unroll
            for (int mt = 0; mt < 4; mt++) {
                int row = wM * 64 + mt * 16 + (lane & 15);
                int ch = kk * 2 + (lane >> 4);
                ldsm_x4(afr[mt], sa + row * 128 + ((ch ^ (row & 7)) << 4));
            }
#pragma unroll
            for (int p = 0; p < 2; p++) {
                int row = wN * 32 + p * 16 + ((lane >> 4) << 3) + (lane & 7);
                int ch = kk * 2 + ((lane >> 3) & 1);
                ldsm_x4(bfr[p], sb + row * 128 + ((ch ^ (row & 7)) << 4));
            }
#pragma unroll
            for (int mt = 0; mt < 4; mt++)
#pragma unroll
                for (int nt = 0; nt < 4; nt++)
                    mma_f16(acc[mt][nt], afr[mt], &bfr[nt >> 1][(nt & 1) * 2]);
        }
    }

    const int g = lane >> 2, t = lane & 3;

    if (!fuse) {
#pragma unroll
        for (int mt = 0; mt < 4; mt++) {
            int r0 = m0 + wM * 64 + mt * 16 + g;
#pragma unroll
            for (int nt = 0; nt < 4; nt++) {
                int cc = n0 + wN * 32 + nt * 8 + t * 2;
                *(float2*)(C + (size_t)r0 * N + cc) =
                    make_float2(acc[mt][nt][0], acc[mt][nt][1]);
                *(float2*)(C + (size_t)(r0 + 8) * N + cc) =
                    make_float2(acc[mt][nt][2], acc[mt][nt][3]);
            }
        }
        return;
    }

    const int nb = blockIdx.x;   // 0..15 q, 16..23 k, 24..31 v
    if (nb >= 24) {
        int head = nb - 24;
        int vc0 = head * 128;
#pragma unroll
        for (int mt = 0; mt < 4; mt++) {
            int r0 = m0 + wM * 64 + mt * 16 + g;
#pragma unroll
            for (int nt = 0; nt < 4; nt++) {
                int cc = vc0 + wN * 32 + nt * 8 + t * 2;
                *(float2*)(vout + (size_t)r0 * (NKV * HD) + cc) =
                    make_float2(acc[mt][nt][0], acc[mt][nt][1]);
                *(float2*)(vout + (size_t)(r0 + 8) * (NKV * HD) + cc) =
                    make_float2(acc[mt][nt][2], acc[mt][nt][3]);
            }
        }
        if (wN == 3) {   // cols 96..127 -> fp16 copy for tensor-PV slice
#pragma unroll
            for (int mt = 0; mt < 4; mt++) {
                int r0 = m0 + wM * 64 + mt * 16 + g;
#pragma unroll
                for (int nt = 0; nt < 4; nt++) {
                    int sc = nt * 8 + t * 2;
                    *(u32*)(vhout + ((size_t)r0 * NKV + head) * 32 + sc) =
                        packh2(acc[mt][nt][0], acc[mt][nt][1]);
                    *(u32*)(vhout + ((size_t)(r0 + 8) * NKV + head) * 32 + sc) =
                        packh2(acc[mt][nt][2], acc[mt][nt][3]);
                }
            }
        }
        return;
    }

    // q/k block: fused RMSNorm + RoPE (stage tile through smem)
    float* Cs = (float*)smc;
    __syncthreads();
#pragma unroll
    for (int mt = 0; mt < 4; mt++) {
        int rl = wM * 64 + mt * 16 + g;
#pragma unroll
        for (int nt = 0; nt < 4; nt++) {
            int cl = wN * 32 + nt * 8 + t * 2;
            *(float2*)&Cs[rl * 132 + cl]       = make_float2(acc[mt][nt][0], acc[mt][nt][1]);
            *(float2*)&Cs[(rl + 8) * 132 + cl] = make_float2(acc[mt][nt][2], acc[mt][nt][3]);
        }
    }
    __syncthreads();

    const bool isQ = (nb < 16);
    const float* w = isQ ? qw : kw;
    const float4 wv = *(const float4*)(w + lane * 4);
    const float sgn = (lane < 16) ? -1.0f : 1.0f;
    const size_t tstream = (lane < 16) ? (size_t)0 : (size_t)S_TOK * HD;

#pragma unroll 4
    for (int rr = 0; rr < 16; rr++) {
        int row = warp * 16 + rr;
        int s = m0 + row;

        float4 x = *(const float4*)&Cs[row * 132 + lane * 4];
        float ss = x.x * x.x + x.y * x.y + x.z * x.z + x.w * x.w;
#pragma unroll
        for (int m = 16; m > 0; m >>= 1) ss += __shfl_xor_sync(0xffffffffu, ss, m);
        float r = rsqrtf(ss * (1.0f / 128.0f) + 1e-6f);

        float xn0 = x.x * r * wv.x, xn1 = x.y * r * wv.y;
        float xn2 = x.z * r * wv.z, xn3 = x.w * r * wv.w;

        float p0 = __shfl_xor_sync(0xffffffffu, xn0, 16);
        float p1 = __shfl_xor_sync(0xffffffffu, xn1, 16);
        float p2 = __shfl_xor_sync(0xffffffffu, xn2, 16);
        float p3 = __shfl_xor_sync(0xffffffffu, xn3, 16);

        size_t toff = tstream + (size_t)s * HD + lane * 4;
        float4 cv = *(const float4*)(cosT + toff);
        float4 sv = *(const float4*)(sinT + toff);

        float ov[4];
        ov[0] = xn0 * cv.x + sgn * p0 * sv.x;
        ov[1] = xn1 * cv.y + sgn * p1 * sv.y;
        ov[2] = xn2 * cv.z + sgn * p2 * sv.z;
        ov[3] = xn3 * cv.w + sgn * p3 * sv.w;

        u64 hp = 0, lp = 0;
#pragma unroll
        for (int j = 0; j < 4; j++) {
            bf16 hb = __float2bfloat16(ov[j]);
            bf16 lb = __float2bfloat16(ov[j] - __bfloat162float(hb));
            hp |= (u64)(*(unsigned short*)&hb) << (16 * j);
            lp |= (u64)(*(unsigned short*)&lb) << (16 * j);
        }
        bf16* dst = isQ ? (qs + ((size_t)s * NH + nb) * 256)
                        : (ks + ((size_t)s * NKV + (nb - 16)) * 256);
        *(u64*)(dst + lane * 4)       = hp;
        *(u64*)(dst + 128 + lane * 4) = lp;
    }
}

// ---------------------------------------------------------------------------
// Warp-specialized flash attention with hybrid PV:
//   S-warps (0-3): bf16 3-term scores + softmax + fp16 tensor PV for cols 96-127
//   V-warps (4-7): fp32 f32x2 PV for cols 0-95
// ---------------------------------------------------------------------------
#define AQS 0
#define AKS 32768
#define AVS 98304
#define APF 163840
#define AAF 198656
#define ALF 199168
#define VSL 199424              // fp16 V-slice: 2 x 64 rows x 80B
#define ATT_SMEM 209664
#define VSTR (NKV * HD)

__global__ __launch_bounds__(256) void attn_tc(
    const bf16* __restrict__ qs, const bf16* __restrict__ ks,
    const float* __restrict__ v, const f16* __restrict__ vh,
    f16* __restrict__ o2)
{
    extern __shared__ char sm[];
    const u32 smb = s2u(sm);
    float* Pf = (float*)(sm + APF);
    float* Af = (float*)(sm + AAF);
    float* Lf = (float*)(sm + ALF);

    const int tid = threadIdx.x;
    const int warp = tid >> 5, lane = tid & 31;
    const bool isS = warp < 4;
    const int qt = blockIdx.x, seg = blockIdx.y, h = blockIdx.z;
    const int hkv = h >> 1;

    const bf16* Qg = qs + ((size_t)(seg * SEGLEN + qt * 64) * NH + h) * 256;
    const bf16* Kg = ks + ((size_t)(seg * SEGLEN) * NKV + hkv) * 256;
    const float* Vg = v + (size_t)(seg * SEGLEN) * VSTR + hkv * HD;
    const f16* Vhg = vh + ((size_t)(seg * SEGLEN) * NKV + hkv) * 32;

#pragma unroll
    for (int j = 0; j < 8; j++) {
        int q = tid + j * 256;
        int r = q >> 5, c = q & 31;
        cp16(smb + AQS + r * 512 + ((c ^ (r & 7)) << 4),
             Qg + (size_t)r * (NH * 256) + c * 8);
    }
    cp_commit();
    if (isS) {
#pragma unroll
        for (int j = 0; j < 16; j++) {
            int q = tid + j * 128;
            int r = q >> 5, c = q & 31;
            cp16(smb + AKS + r * 512 + ((c ^ (r & 7)) << 4),
                 Kg + (size_t)r * (NKV * 256) + c * 8);
        }
#pragma unroll
        for (int j = 0; j < 2; j++) {            // V-slice fp16: 64 rows x 64B
            int q = tid + j * 128;
            int r = q >> 2, sg = q & 3;
            cp16(smb + VSL + r * 80 + sg * 16,
                 Vhg + (size_t)r * (NKV * 32) + sg * 8);
        }
        cp_commit();
    } else {
        int vt = tid - 128;
#pragma unroll
        for (int j = 0; j < 16; j++) {
            int q = vt + j * 128;
            int r = q >> 5, c = q & 31;
            cp16(smb + AVS + r * 512 + c * 16, Vg + (size_t)r * VSTR + c * 4);
        }
        cp_commit();
    }

    const int g = lane >> 2, t = lane & 3;
    float m0 = -INFINITY, m1 = -INFINITY, l0 = 0.f, l1 = 0.f;   // S state
    float osl[4][4];                                            // S tensor-PV acc
#pragma unroll
    for (int n = 0; n < 4; n++)
#pragma unroll
        for (int c = 0; c < 4; c++) osl[n][c] = 0.f;

    u64 O2[8][3];                                               // V state (96 cols)
#pragma unroll
    for (int i = 0; i < 8; i++)
#pragma unroll
        for (int j = 0; j < 3; j++) O2[i][j] = 0ULL;
    const int vt = tid - 128;
    const int tx = vt & 15, ty = vt >> 4;

    for (int it = 0; it <= 16; it++) {
        asm volatile("cp.async.wait_group 0;" ::: "memory");
        __syncthreads();

        if (isS && it < 16) {
            if (it + 1 < 16) {
                u32 kd = smb + AKS + ((it + 1) & 1) * 32768;
#pragma unroll
                for (int j = 0; j < 16; j++) {
                    int q = tid + j * 128;
                    int r = q >> 5, c = q & 31;
                    cp16(kd + r * 512 + ((c ^ (r & 7)) << 4),
                         Kg + (size_t)((it + 1) * 64 + r) * (NKV * 256) + c * 8);
                }
                u32 vsd = smb + VSL + ((it + 1) & 1) * 5120;
#pragma unroll
                for (int j = 0; j < 2; j++) {
                    int q = tid + j * 128;
                    int r = q >> 2, sg = q & 3;
                    cp16(vsd + r * 80 + sg * 16,
                         Vhg + (size_t)((it + 1) * 64 + r) * (NKV * 32) + sg * 8);
                }
                cp_commit();
            }
            u32 kb = smb + AKS + (it & 1) * 32768;
            float acc[8][4];
#pragma unroll
            for (int n = 0; n < 8; n++)
#pragma unroll
                for (int c = 0; c < 4; c++) acc[n][c] = 0.f;

            const int ABASE[3] = {0, 16, 0};
            const int BBASE[3] = {0, 0, 16};
#pragma unroll
            for (int p = 0; p < 3; p++) {
#pragma unroll
                for (int k = 0; k < 8; k++) {
                    u32 afr[4], bfr[4][4];
                    int ar = warp * 16 + (lane & 15);
                    int ac = ABASE[p] + 2 * k + (lane >> 4);
                    ldsm_x4(afr, smb + AQS + ar * 512 + ((ac ^ (ar & 7)) << 4));
#pragma unroll
                    for (int pg = 0; pg < 4; pg++) {
                        int br = pg * 16 + ((lane >> 4) << 3) + (lane & 7);
                        int bc = BBASE[p] + 2 * k + ((lane >> 3) & 1);
                        ldsm_x4(bfr[pg], kb + br * 512 + ((bc ^ (br & 7)) << 4));
                    }
#pragma unroll
                    for (int nt = 0; nt < 8; nt++)
                        mma_bf16(acc[nt], afr, &bfr[nt >> 1][(nt & 1) * 2]);
                }
            }
            // ---- online softmax ----
            float mx0 = -INFINITY, mx1 = -INFINITY;
#pragma unroll
            for (int n = 0; n < 8; n++) {
#pragma unroll
                for (int c = 0; c < 4; c++) acc[n][c] *= SCALE;
                mx0 = fmaxf(mx0, fmaxf(acc[n][0], acc[n][1]));
                mx1 = fmaxf(mx1, fmaxf(acc[n][2], acc[n][3]));
            }
            mx0 = fmaxf(mx0, __shfl_xor_sync(0xffffffffu, mx0, 1));
            mx0 = fmaxf(mx0, __shfl_xor_sync(0xffffffffu, mx0, 2));
            mx1 = fmaxf(mx1, __shfl_xor_sync(0xffffffffu, mx1, 1));
            mx1 = fmaxf(mx1, __shfl_xor_sync(0xffffffffu, mx1, 2));
            float mn0 = fmaxf(m0, mx0), mn1 = fmaxf(m1, mx1);
            float a0 = __expf(m0 - mn0), a1 = __expf(m1 - mn1);
            m0 = mn0; m1 = mn1;
            float s0 = 0.f, s1 = 0.f;
#pragma unroll
            for (int n = 0; n < 8; n++) {
                acc[n][0] = __expf(acc[n][0] - mn0); s0 += acc[n][0];
                acc[n][1] = __expf(acc[n][1] - mn0); s0 += acc[n][1];
                acc[n][2] = __expf(acc[n][2] - mn1); s1 += acc[n][2];
                acc[n][3] = __expf(acc[n][3] - mn1); s1 += acc[n][3];
            }
            s0 += __shfl_xor_sync(0xffffffffu, s0, 1);
            s0 += __shfl_xor_sync(0xffffffffu, s0, 2);
            s1 += __shfl_xor_sync(0xffffffffu, s1, 1);
            s1 += __shfl_xor_sync(0xffffffffu, s1, 2);
            l0 = l0 * a0 + s0;
            l1 = l1 * a1 + s1;

            int r0 = warp * 16 + g, r1 = r0 + 8;
            float* Pb = Pf + (it & 1) * (64 * 68);
#pragma unroll
            for (int n = 0; n < 8; n++) {
                *(float2*)&Pb[r0 * 68 + n * 8 + t * 2] = make_float2(acc[n][0], acc[n][1]);
                *(float2*)&Pb[r1 * 68 + n * 8 + t * 2] = make_float2(acc[n][2], acc[n][3]);
            }
            if (t == 0) {
                Af[(it & 1) * 64 + r0] = a0;
                Af[(it & 1) * 64 + r1] = a1;
                if (it == 15) { Lf[r0] = l0; Lf[r1] = l1; }
            }

            // ---- tensor PV slice: cols 96..127, P from registers ----
#pragma unroll
            for (int n = 0; n < 4; n++) {
                osl[n][0] *= a0; osl[n][1] *= a0;
                osl[n][2] *= a1; osl[n][3] *= a1;
            }
            u32 vsb = smb + VSL + (it & 1) * 5120;
#pragma unroll
            for (int kk = 0; kk < 4; kk++) {
                u32 pa[4];
                pa[0] = packh2(acc[2 * kk][0],     acc[2 * kk][1]);
                pa[1] = packh2(acc[2 * kk][2],     acc[2 * kk][3]);
                pa[2] = packh2(acc[2 * kk + 1][0], acc[2 * kk + 1][1]);
                pa[3] = packh2(acc[2 * kk + 1][2], acc[2 * kk + 1][3]);
                u32 vb0[4], vb1[4];
                u32 base = vsb + (kk * 16 + (lane & 15)) * 80 + ((lane >> 4) << 4);
                ldsm_x4_t(vb0, base);
                ldsm_x4_t(vb1, base + 32);
                mma_f16(osl[0], pa, vb0);
                mma_f16(osl[1], pa, vb0 + 2);
                mma_f16(osl[2], pa, vb1);
                mma_f16(osl[3], pa, vb1 + 2);
            }
        }

        if (!isS && it > 0) {
            int j = it - 1;
            if (it < 16) {
                u32 vd = smb + AVS + (it & 1) * 32768;
#pragma unroll
                for (int jj = 0; jj < 16; jj++) {
                    int q = vt + jj * 128;
                    int r = q >> 5, c = q & 31;
                    cp16(vd + r * 512 + c * 16,
                         Vg + (size_t)(it * 64 + r) * VSTR + c * 4);
                }
                cp_commit();
            }
            const float* Pb = Pf + (j & 1) * (64 * 68);
            const char* Vb = sm + AVS + (j & 1) * 32768;
#pragma unroll
            for (int ii = 0; ii < 8; ii++) {
                float a = Af[(j & 1) * 64 + ty * 8 + ii];
                u64 ad = pack2(a, a);
#pragma unroll
                for (int c = 0; c < 3; c++) O2[ii][c] = mul2(O2[ii][c], ad);
            }
#pragma unroll 2
            for (int j4 = 0; j4 < 16; j4++) {
                float pv[8][4];
#pragma unroll
                for (int ii = 0; ii < 8; ii++) {
                    float4 tmp = *(const float4*)&Pb[(ty * 8 + ii) * 68 + j4 * 4];
                    pv[ii][0] = tmp.x; pv[ii][1] = tmp.y;
                    pv[ii][2] = tmp.z; pv[ii][3] = tmp.w;
                }
#pragma unroll
                for (int e = 0; e < 4; e++) {
                    const u64* vr = (const u64*)(Vb + ((j4 * 4 + e) * 128 + tx * 6) * 4);
                    u64 v0 = vr[0], v1 = vr[1], v2 = vr[2];
#pragma unroll
                    for (int ii = 0; ii < 8; ii++) {
                        u64 pd = pack2(pv[ii][e], pv[ii][e]);
                        fma2(O2[ii][0], pd, v0);
                        fma2(O2[ii][1], pd, v1);
                        fma2(O2[ii][2], pd, v2);
                    }
                }
            }
        }
    }

    if (isS) {
        // S-warp epilogue: cols 96..127 for rows warp*16+g, +8
        float inv0 = 1.0f / l0, inv1 = 1.0f / l1;
        int gr0 = seg * SEGLEN + qt * 64 + warp * 16 + g;
#pragma unroll
        for (int n = 0; n < 4; n++) {
            int col = h * HD + 96 + n * 8 + t * 2;
            float v00 = osl[n][0] * inv0, v01 = osl[n][1] * inv0;
            float v10 = osl[n][2] * inv1, v11 = osl[n][3] * inv1;
            f16 h00 = __float2half(v00), h01 = __float2half(v01);
            f16 h10 = __float2half(v10), h11 = __float2half(v11);
            f16* p0 = o2 + (size_t)gr0 * KP2 + col;
            f16* p1 = o2 + (size_t)(gr0 + 8) * KP2 + col;
            *(u32*)p0 = (u32)(*(unsigned short*)&h00) | ((u32)(*(unsigned short*)&h01) << 16);
            *(u32*)p1 = (u32)(*(unsigned short*)&h10) | ((u32)(*(unsigned short*)&h11) << 16);
            *(u32*)(p0 + OD) = packh2(v00 - __half2float(h00), v01 - __half2float(h01));
            *(u32*)(p1 + OD) = packh2(v10 - __half2float(h10), v11 - __half2float(h11));
        }
    } else {
        // V-warp epilogue: cols 0..95 (6 per tx lane)
#pragma unroll
        for (int ii = 0; ii < 8; ii++) {
            int row = ty * 8 + ii;
            float inv = 1.0f / Lf[row];
            float ov[6];
#pragma unroll
            for (int c = 0; c < 3; c++) {
                float lo, hi; unpack2(O2[ii][c], lo, hi);
                ov[2 * c] = lo * inv; ov[2 * c + 1] = hi * inv;
            }
            f16* orow = o2 + (size_t)(seg * SEGLEN + qt * 64 + row) * KP2 + h * HD + tx * 6;
#pragma unroll
            for (int c = 0; c < 3; c++) {
                float a0 = ov[2 * c], a1 = ov[2 * c + 1];
                f16 h0 = __float2half(a0), h1 = __float2half(a1);
                *(u32*)(orow + 2 * c) =
                    (u32)(*(unsigned short*)&h0) | ((u32)(*(unsigned short*)&h1) << 16);
                *(u32*)(orow + OD + 2 * c) =
                    packh2(a0 - __half2float(h0), a1 - __half2float(h1));
            }
        }
    }
}

// ---------------------------------------------------------------------------
extern "C" void kernel_launch(void* const* d_in, const int* in_sizes, int n_in,
                              void* d_out, int out_size)
{
    const float* x    = (const float*)d_in[0];
    const float* cosT = (const float*)d_in[2];
    const float* sinT = (const float*)d_in[3];
    const float* Wq   = (const float*)d_in[4];
    const float* Wk   = (const float*)d_in[5];
    const float* Wv   = (const float*)d_in[6];
    const float* Wo   = (const float*)d_in[7];
    const float* qw   = (const float*)d_in[8];
    const float* kw   = (const float*)d_in[9];
    float* out = (float*)d_out;

    f16 *x2, *w2, *o2, *wo2, *vhp;
    bf16 *qsp, *ksp;
    float *vp;
    cudaGetSymbolAddress((void**)&x2,  g_x2);
    cudaGetSymbolAddress((void**)&w2,  g_w2);
    cudaGetSymbolAddress((void**)&o2,  g_o2);
    cudaGetSymbolAddress((void**)&wo2, g_wo2);
    cudaGetSymbolAddress((void**)&qsp, g_qs);
    cudaGetSymbolAddress((void**)&ksp, g_ks);
    cudaGetSymbolAddress((void**)&vp,  g_v);
    cudaGetSymbolAddress((void**)&vhp, g_vh);

    cudaFuncSetAttribute(gemm_mma,
        cudaFuncAttributeMaxDynamicSharedMemorySize, GEMM_SMEM);
    cudaFuncSetAttribute(attn_tc,
        cudaFuncAttributeMaxDynamicSharedMemorySize, ATT_SMEM);

    // launches 0-4: conversions
    {
        int t4 = S_TOK * HID / 4;
        cvt_split<<<(t4 + 255) / 256, 256>>>(x, x2, HID, 0, t4);
        t4 = 2048 * HID / 4;
        cvt_split<<<(t4 + 255) / 256, 256>>>(Wq, w2, HID, 1, t4);
        t4 = 1024 * HID / 4;
        cvt_split<<<(t4 + 255) / 256, 256>>>(Wk, w2 + (size_t)2048 * KP1, HID, 1, t4);
        cvt_split<<<(t4 + 255) / 256, 256>>>(Wv, w2 + (size_t)3072 * KP1, HID, 1, t4);
        t4 = HID * OD / 4;
        cvt_split<<<(t4 + 255) / 256, 256>>>(Wo, wo2, OD, 1, t4);
    }

    // QKV projection with fused RMSNorm+RoPE / V-split epilogue
    gemm_mma<<<dim3(QKVD / 128, S_TOK / 128), 256, GEMM_SMEM>>>(
        x2, w2, nullptr, QKVD, KP1, 1, qsp, ksp, vp, vhp, cosT, sinT, qw, kw);

    // hybrid tensor/fma attention
    attn_tc<<<dim3(16, 8, 16), 256, ATT_SMEM>>>(qsp, ksp, vp, vhp, o2);

    // output projection
    gemm_mma<<<dim3(HID / 128, S_TOK / 128), 256, GEMM_SMEM>>>(
        o2, wo2, out, HID, KP2, 0, nullptr, nullptr, nullptr, nullptr,
        nullptr, nullptr, nullptr, nullptr);
}

// round 12
// speedup vs baseline: 1.8234x; 1.2024x over previous
#include <cuda_runtime.h>
#include <cuda_bf16.h>
#include <cuda_fp16.h>
#include <math.h>
#include <cstdint>

#define S_TOK  8192
#define HID    1024
#define NH     16
#define NKV    8
#define HD     128
#define SEGLEN 1024
#define QKVD   4096
#define OD     2048
#define SCALE  0.08838834764831845f

typedef unsigned long long u64;
typedef unsigned int u32;
typedef __nv_bfloat16 bf16;
typedef __half f16;

// ---------------- scratch -----------------------------------------------
__device__ f16   g_x2 [S_TOK * HID];      // x fp16 [8192,1024]
__device__ f16   g_w2 [QKVD  * HID];      // Wq|Wk|Wv fp16 [4096,1024]
__device__ bf16  g_qs [S_TOK * NH  * 256];// Q split bf16 [S][16][hi128|lo128]
__device__ bf16  g_ks [S_TOK * NKV * 256];// K split bf16 [S][8][hi128|lo128]
__device__ float g_v  [S_TOK * NKV * HD]; // V fp32 packed [S][8][128]
__device__ f16   g_vh [S_TOK * NKV * 32]; // V cols 96..127 fp16 [S][8][32]
__device__ f16   g_o2 [S_TOK * OD];       // attn out fp16 [8192,2048]
__device__ f16   g_wo2[HID * OD];         // Wo fp16 [1024,2048]

// ---------------- helpers ------------------------------------------------
__device__ __forceinline__ u64 pack2(float a, float b) {
    u64 r; asm("mov.b64 %0,{%1,%2};" : "=l"(r) : "f"(a), "f"(b)); return r;
}
__device__ __forceinline__ void unpack2(u64 v, float& a, float& b) {
    asm("mov.b64 {%0,%1},%2;" : "=f"(a), "=f"(b) : "l"(v));
}
__device__ __forceinline__ void fma2(u64& c, u64 a, u64 b) {
    asm("fma.rn.f32x2 %0,%1,%2,%3;" : "=l"(c) : "l"(a), "l"(b), "l"(c));
}
__device__ __forceinline__ u64 mul2(u64 a, u64 b) {
    u64 r; asm("mul.rn.f32x2 %0,%1,%2;" : "=l"(r) : "l"(a), "l"(b)); return r;
}
__device__ __forceinline__ u32 s2u(const void* p) {
    u32 a; asm("{ .reg .u64 t; cvta.to.shared.u64 t,%1; cvt.u32.u64 %0,t; }"
               : "=r"(a) : "l"(p));
    return a;
}
__device__ __forceinline__ void cp16(u32 dst, const void* src) {
    asm volatile("cp.async.cg.shared.global [%0],[%1],16;" :: "r"(dst), "l"(src));
}
__device__ __forceinline__ void cp_commit() {
    asm volatile("cp.async.commit_group;" ::: "memory");
}
__device__ __forceinline__ void ldsm_x4(u32* r, u32 addr) {
    asm volatile("ldmatrix.sync.aligned.m8n8.x4.shared.b16 {%0,%1,%2,%3},[%4];"
                 : "=r"(r[0]), "=r"(r[1]), "=r"(r[2]), "=r"(r[3]) : "r"(addr));
}
__device__ __forceinline__ void ldsm_x4_t(u32* r, u32 addr) {
    asm volatile("ldmatrix.sync.aligned.m8n8.x4.trans.shared.b16 {%0,%1,%2,%3},[%4];"
                 : "=r"(r[0]), "=r"(r[1]), "=r"(r[2]), "=r"(r[3]) : "r"(addr));
}
__device__ __forceinline__ void mma_bf16(float* d, const u32* a, const u32* b) {
    asm volatile(
        "mma.sync.aligned.m16n8k16.row.col.f32.bf16.bf16.f32 "
        "{%0,%1,%2,%3},{%4,%5,%6,%7},{%8,%9},{%0,%1,%2,%3};"
        : "+f"(d[0]), "+f"(d[1]), "+f"(d[2]), "+f"(d[3])
        : "r"(a[0]), "r"(a[1]), "r"(a[2]), "r"(a[3]), "r"(b[0]), "r"(b[1]));
}
__device__ __forceinline__ void mma_f16(float* d, const u32* a, const u32* b) {
    asm volatile(
        "mma.sync.aligned.m16n8k16.row.col.f32.f16.f16.f32 "
        "{%0,%1,%2,%3},{%4,%5,%6,%7},{%8,%9},{%0,%1,%2,%3};"
        : "+f"(d[0]), "+f"(d[1]), "+f"(d[2]), "+f"(d[3])
        : "r"(a[0]), "r"(a[1]), "r"(a[2]), "r"(a[3]), "r"(b[0]), "r"(b[1]));
}
__device__ __forceinline__ u32 packh2(float a, float b) {
    u32 r; asm("cvt.rn.f16x2.f32 %0,%1,%2;" : "=r"(r) : "f"(b), "f"(a));
    return r;
}

// ---------------------------------------------------------------------------
// plain fp16 conversion: src fp32 [n*8] -> dst f16 [n*8]
// ---------------------------------------------------------------------------
__global__ __launch_bounds__(256) void cvt_f16(
    const float* __restrict__ src, f16* __restrict__ dst, int total8)
{
    int i = blockIdx.x * blockDim.x + threadIdx.x;
    if (i >= total8) return;
    float4 v0 = *(const float4*)(src + (size_t)i * 8);
    float4 v1 = *(const float4*)(src + (size_t)i * 8 + 4);
    uint4 o;
    o.x = packh2(v0.x, v0.y); o.y = packh2(v0.z, v0.w);
    o.z = packh2(v1.x, v1.y); o.w = packh2(v1.z, v1.w);
    *(uint4*)(dst + (size_t)i * 8) = o;
}

// ---------------------------------------------------------------------------
// mma.sync GEMM (R9/R11-proven mainloop): C = A[M,Kp] f16 @ B[N,Kp]^T f16
// fuse==0: plain fp32 epilogue. fuse==1: QKV epilogue (norm+rope / V stores).
// ---------------------------------------------------------------------------
#define GSTAGE 32768
#define GEMM_SMEM (3 * GSTAGE)

__global__ __launch_bounds__(256) void gemm_mma(
    const f16* __restrict__ A, const f16* __restrict__ B,
    float* __restrict__ C, int N, int Kp, int fuse,
    bf16* __restrict__ qs, bf16* __restrict__ ks,
    float* __restrict__ vout, f16* __restrict__ vhout,
    const float* __restrict__ cosT, const float* __restrict__ sinT,
    const float* __restrict__ qw, const float* __restrict__ kw)
{
    extern __shared__ char smc[];
    const u32 smb = s2u(smc);
    const int tid = threadIdx.x;
    const int warp = tid >> 5, lane = tid & 31;
    const int wM = warp >> 2, wN = warp & 3;
    const int m0 = blockIdx.y << 7, n0 = blockIdx.x << 7;
    const int chunks = Kp >> 6;

    const f16* Ag = A + (size_t)m0 * Kp;
    const f16* Bg = B + (size_t)n0 * Kp;

    float acc[4][4][4];
#pragma unroll
    for (int a = 0; a < 4; a++)
#pragma unroll
        for (int b = 0; b < 4; b++)
#pragma unroll
            for (int c = 0; c < 4; c++) acc[a][b][c] = 0.f;

    auto load_stage = [&](int st, int ch) {
        u32 sa = smb + st * GSTAGE;
        u32 sb = sa + 16384;
#pragma unroll
        for (int j = 0; j < 4; j++) {
            int q = tid + j * 256;
            int r = q >> 3, c = q & 7;
            cp16(sa + r * 128 + ((c ^ (r & 7)) << 4),
                 Ag + (size_t)r * Kp + ch * 64 + c * 8);
        }
#pragma unroll
        for (int j = 0; j < 4; j++) {
            int q = tid + j * 256;
            int r = q >> 3, c = q & 7;
            cp16(sb + r * 128 + ((c ^ (r & 7)) << 4),
                 Bg + (size_t)r * Kp + ch * 64 + c * 8);
        }
        cp_commit();
    };

    load_stage(0, 0);
    load_stage(1, 1);

    for (int i = 0; i < chunks; i++) {
        int s = i % 3;
        asm volatile("cp.async.wait_group 1;" ::: "memory");
        __syncthreads();
        if (i + 2 < chunks) load_stage((i + 2) % 3, i + 2);
        else cp_commit();

        u32 sa = smb + s * GSTAGE;
        u32 sb = sa + 16384;
#pragma unroll
        for (int kk = 0; kk < 4; kk++) {
            u32 afr[4][4], bfr[2][4];
#pragma unroll
            for (int mt = 0; mt < 4; mt++) {
                int row = wM * 64 + mt * 16 + (lane & 15);
                int ch = kk * 2 + (lane >> 4);
                ldsm_x4(afr[mt], sa + row * 128 + ((ch ^ (row & 7)) << 4));
            }
#pragma unroll
            for (int p = 0; p < 2; p++) {
                int row = wN * 32 + p * 16 + ((lane >> 4) << 3) + (lane & 7);
                int ch = kk * 2 + ((lane >> 3) & 1);
                ldsm_x4(bfr[p], sb + row * 128 + ((ch ^ (row & 7)) << 4));
            }
#pragma unroll
            for (int mt = 0; mt < 4; mt++)
#pragma unroll
                for (int nt = 0; nt < 4; nt++)
                    mma_f16(acc[mt][nt], afr[mt], &bfr[nt >> 1][(nt & 1) * 2]);
        }
    }

    const int g = lane >> 2, t = lane & 3;

    if (!fuse) {
#pragma unroll
        for (int mt = 0; mt < 4; mt++) {
            int r0 = m0 + wM * 64 + mt * 16 + g;
#pragma unroll
            for (int nt = 0; nt < 4; nt++) {
                int cc = n0 + wN * 32 + nt * 8 + t * 2;
                *(float2*)(C + (size_t)r0 * N + cc) =
                    make_float2(acc[mt][nt][0], acc[mt][nt][1]);
                *(float2*)(C + (size_t)(r0 + 8) * N + cc) =
                    make_float2(acc[mt][nt][2], acc[mt][nt][3]);
            }
        }
        return;
    }

    const int nb = blockIdx.x;   // 0..15 q, 16..23 k, 24..31 v
    if (nb >= 24) {
        int head = nb - 24;
        int vc0 = head * 128;
#pragma unroll
        for (int mt = 0; mt < 4; mt++) {
            int r0 = m0 + wM * 64 + mt * 16 + g;
#pragma unroll
            for (int nt = 0; nt < 4; nt++) {
                int cc = vc0 + wN * 32 + nt * 8 + t * 2;
                *(float2*)(vout + (size_t)r0 * (NKV * HD) + cc) =
                    make_float2(acc[mt][nt][0], acc[mt][nt][1]);
                *(float2*)(vout + (size_t)(r0 + 8) * (NKV * HD) + cc) =
                    make_float2(acc[mt][nt][2], acc[mt][nt][3]);
            }
        }
        if (wN == 3) {   // cols 96..127 -> fp16 copy for tensor-PV slice
#pragma unroll
            for (int mt = 0; mt < 4; mt++) {
                int r0 = m0 + wM * 64 + mt * 16 + g;
#pragma unroll
                for (int nt = 0; nt < 4; nt++) {
                    int sc = nt * 8 + t * 2;
                    *(u32*)(vhout + ((size_t)r0 * NKV + head) * 32 + sc) =
                        packh2(acc[mt][nt][0], acc[mt][nt][1]);
                    *(u32*)(vhout + ((size_t)(r0 + 8) * NKV + head) * 32 + sc) =
                        packh2(acc[mt][nt][2], acc[mt][nt][3]);
                }
            }
        }
        return;
    }

    // q/k block: fused RMSNorm + RoPE (stage tile through smem)
    float* Cs = (float*)smc;
    __syncthreads();
#pragma unroll
    for (int mt = 0; mt < 4; mt++) {
        int rl = wM * 64 + mt * 16 + g;
#pragma unroll
        for (int nt = 0; nt < 4; nt++) {
            int cl = wN * 32 + nt * 8 + t * 2;
            *(float2*)&Cs[rl * 132 + cl]       = make_float2(acc[mt][nt][0], acc[mt][nt][1]);
            *(float2*)&Cs[(rl + 8) * 132 + cl] = make_float2(acc[mt][nt][2], acc[mt][nt][3]);
        }
    }
    __syncthreads();

    const bool isQ = (nb < 16);
    const float* w = isQ ? qw : kw;
    const float4 wv = *(const float4*)(w + lane * 4);
    const float sgn = (lane < 16) ? -1.0f : 1.0f;
    const size_t tstream = (lane < 16) ? (size_t)0 : (size_t)S_TOK * HD;

#pragma unroll 4
    for (int rr = 0; rr < 16; rr++) {
        int row = warp * 16 + rr;
        int s = m0 + row;

        float4 x = *(const float4*)&Cs[row * 132 + lane * 4];
        float ss = x.x * x.x + x.y * x.y + x.z * x.z + x.w * x.w;
#pragma unroll
        for (int m = 16; m > 0; m >>= 1) ss += __shfl_xor_sync(0xffffffffu, ss, m);
        float r = rsqrtf(ss * (1.0f / 128.0f) + 1e-6f);

        float xn0 = x.x * r * wv.x, xn1 = x.y * r * wv.y;
        float xn2 = x.z * r * wv.z, xn3 = x.w * r * wv.w;

        float p0 = __shfl_xor_sync(0xffffffffu, xn0, 16);
        float p1 = __shfl_xor_sync(0xffffffffu, xn1, 16);
        float p2 = __shfl_xor_sync(0xffffffffu, xn2, 16);
        float p3 = __shfl_xor_sync(0xffffffffu, xn3, 16);

        size_t toff = tstream + (size_t)s * HD + lane * 4;
        float4 cv = *(const float4*)(cosT + toff);
        float4 sv = *(const float4*)(sinT + toff);

        float ov[4];
        ov[0] = xn0 * cv.x + sgn * p0 * sv.x;
        ov[1] = xn1 * cv.y + sgn * p1 * sv.y;
        ov[2] = xn2 * cv.z + sgn * p2 * sv.z;
        ov[3] = xn3 * cv.w + sgn * p3 * sv.w;

        u64 hp = 0, lp = 0;
#pragma unroll
        for (int j = 0; j < 4; j++) {
            bf16 hb = __float2bfloat16(ov[j]);
            bf16 lb = __float2bfloat16(ov[j] - __bfloat162float(hb));
            hp |= (u64)(*(unsigned short*)&hb) << (16 * j);
            lp |= (u64)(*(unsigned short*)&lb) << (16 * j);
        }
        bf16* dst = isQ ? (qs + ((size_t)s * NH + nb) * 256)
                        : (ks + ((size_t)s * NKV + (nb - 16)) * 256);
        *(u64*)(dst + lane * 4)       = hp;
        *(u64*)(dst + 128 + lane * 4) = lp;
    }
}

// ---------------------------------------------------------------------------
// Warp-specialized flash attention with hybrid PV (R11-proven).
// Output: plain fp16 [S,2048].
// ---------------------------------------------------------------------------
#define AQS 0
#define AKS 32768
#define AVS 98304
#define APF 163840
#define AAF 198656
#define ALF 199168
#define VSL 199424
#define ATT_SMEM 209664
#define VSTR (NKV * HD)

__global__ __launch_bounds__(256) void attn_tc(
    const bf16* __restrict__ qs, const bf16* __restrict__ ks,
    const float* __restrict__ v, const f16* __restrict__ vh,
    f16* __restrict__ o2)
{
    extern __shared__ char sm[];
    const u32 smb = s2u(sm);
    float* Pf = (float*)(sm + APF);
    float* Af = (float*)(sm + AAF);
    float* Lf = (float*)(sm + ALF);

    const int tid = threadIdx.x;
    const int warp = tid >> 5, lane = tid & 31;
    const bool isS = warp < 4;
    const int qt = blockIdx.x, seg = blockIdx.y, h = blockIdx.z;
    const int hkv = h >> 1;

    const bf16* Qg = qs + ((size_t)(seg * SEGLEN + qt * 64) * NH + h) * 256;
    const bf16* Kg = ks + ((size_t)(seg * SEGLEN) * NKV + hkv) * 256;
    const float* Vg = v + (size_t)(seg * SEGLEN) * VSTR + hkv * HD;
    const f16* Vhg = vh + ((size_t)(seg * SEGLEN) * NKV + hkv) * 32;

#pragma unroll
    for (int j = 0; j < 8; j++) {
        int q = tid + j * 256;
        int r = q >> 5, c = q & 31;
        cp16(smb + AQS + r * 512 + ((c ^ (r & 7)) << 4),
             Qg + (size_t)r * (NH * 256) + c * 8);
    }
    cp_commit();
    if (isS) {
#pragma unroll
        for (int j = 0; j < 16; j++) {
            int q = tid + j * 128;
            int r = q >> 5, c = q & 31;
            cp16(smb + AKS + r * 512 + ((c ^ (r & 7)) << 4),
                 Kg + (size_t)r * (NKV * 256) + c * 8);
        }
#pragma unroll
        for (int j = 0; j < 2; j++) {
            int q = tid + j * 128;
            int r = q >> 2, sg = q & 3;
            cp16(smb + VSL + r * 80 + sg * 16,
                 Vhg + (size_t)r * (NKV * 32) + sg * 8);
        }
        cp_commit();
    } else {
        int vt = tid - 128;
#pragma unroll
        for (int j = 0; j < 16; j++) {
            int q = vt + j * 128;
            int r = q >> 5, c = q & 31;
            cp16(smb + AVS + r * 512 + c * 16, Vg + (size_t)r * VSTR + c * 4);
        }
        cp_commit();
    }

    const int g = lane >> 2, t = lane & 3;
    float m0 = -INFINITY, m1 = -INFINITY, l0 = 0.f, l1 = 0.f;
    float osl[4][4];
#pragma unroll
    for (int n = 0; n < 4; n++)
#pragma unroll
        for (int c = 0; c < 4; c++) osl[n][c] = 0.f;

    u64 O2[8][3];
#pragma unroll
    for (int i = 0; i < 8; i++)
#pragma unroll
        for (int j = 0; j < 3; j++) O2[i][j] = 0ULL;
    const int vt = tid - 128;
    const int tx = vt & 15, ty = vt >> 4;

    for (int it = 0; it <= 16; it++) {
        asm volatile("cp.async.wait_group 0;" ::: "memory");
        __syncthreads();

        if (isS && it < 16) {
            if (it + 1 < 16) {
                u32 kd = smb + AKS + ((it + 1) & 1) * 32768;
#pragma unroll
                for (int j = 0; j < 16; j++) {
                    int q = tid + j * 128;
                    int r = q >> 5, c = q & 31;
                    cp16(kd + r * 512 + ((c ^ (r & 7)) << 4),
                         Kg + (size_t)((it + 1) * 64 + r) * (NKV * 256) + c * 8);
                }
                u32 vsd = smb + VSL + ((it + 1) & 1) * 5120;
#pragma unroll
                for (int j = 0; j < 2; j++) {
                    int q = tid + j * 128;
                    int r = q >> 2, sg = q & 3;
                    cp16(vsd + r * 80 + sg * 16,
                         Vhg + (size_t)((it + 1) * 64 + r) * (NKV * 32) + sg * 8);
                }
                cp_commit();
            }
            u32 kb = smb + AKS + (it & 1) * 32768;
            float acc[8][4];
#pragma unroll
            for (int n = 0; n < 8; n++)
#pragma unroll
                for (int c = 0; c < 4; c++) acc[n][c] = 0.f;

            const int ABASE[3] = {0, 16, 0};
            const int BBASE[3] = {0, 0, 16};
#pragma unroll
            for (int p = 0; p < 3; p++) {
#pragma unroll
                for (int k = 0; k < 8; k++) {
                    u32 afr[4], bfr[4][4];
                    int ar = warp * 16 + (lane & 15);
                    int ac = ABASE[p] + 2 * k + (lane >> 4);
                    ldsm_x4(afr, smb + AQS + ar * 512 + ((ac ^ (ar & 7)) << 4));
#pragma unroll
                    for (int pg = 0; pg < 4; pg++) {
                        int br = pg * 16 + ((lane >> 4) << 3) + (lane & 7);
                        int bc = BBASE[p] + 2 * k + ((lane >> 3) & 1);
                        ldsm_x4(bfr[pg], kb + br * 512 + ((bc ^ (br & 7)) << 4));
                    }
#pragma unroll
                    for (int nt = 0; nt < 8; nt++)
                        mma_bf16(acc[nt], afr, &bfr[nt >> 1][(nt & 1) * 2]);
                }
            }
            float mx0 = -INFINITY, mx1 = -INFINITY;
#pragma unroll
            for (int n = 0; n < 8; n++) {
#pragma unroll
                for (int c = 0; c < 4; c++) acc[n][c] *= SCALE;
                mx0 = fmaxf(mx0, fmaxf(acc[n][0], acc[n][1]));
                mx1 = fmaxf(mx1, fmaxf(acc[n][2], acc[n][3]));
            }
            mx0 = fmaxf(mx0, __shfl_xor_sync(0xffffffffu, mx0, 1));
            mx0 = fmaxf(mx0, __shfl_xor_sync(0xffffffffu, mx0, 2));
            mx1 = fmaxf(mx1, __shfl_xor_sync(0xffffffffu, mx1, 1));
            mx1 = fmaxf(mx1, __shfl_xor_sync(0xffffffffu, mx1, 2));
            float mn0 = fmaxf(m0, mx0), mn1 = fmaxf(m1, mx1);
            float a0 = __expf(m0 - mn0), a1 = __expf(m1 - mn1);
            m0 = mn0; m1 = mn1;
            float s0 = 0.f, s1 = 0.f;
#pragma unroll
            for (int n = 0; n < 8; n++) {
                acc[n][0] = __expf(acc[n][0] - mn0); s0 += acc[n][0];
                acc[n][1] = __expf(acc[n][1] - mn0); s0 += acc[n][1];
                acc[n][2] = __expf(acc[n][2] - mn1); s1 += acc[n][2];
                acc[n][3] = __expf(acc[n][3] - mn1); s1 += acc[n][3];
            }
            s0 += __shfl_xor_sync(0xffffffffu, s0, 1);
            s0 += __shfl_xor_sync(0xffffffffu, s0, 2);
            s1 += __shfl_xor_sync(0xffffffffu, s1, 1);
            s1 += __shfl_xor_sync(0xffffffffu, s1, 2);
            l0 = l0 * a0 + s0;
            l1 = l1 * a1 + s1;

            int r0 = warp * 16 + g, r1 = r0 + 8;
            float* Pb = Pf + (it & 1) * (64 * 68);
#pragma unroll
            for (int n = 0; n < 8; n++) {
                *(float2*)&Pb[r0 * 68 + n * 8 + t * 2] = make_float2(acc[n][0], acc[n][1]);
                *(float2*)&Pb[r1 * 68 + n * 8 + t * 2] = make_float2(acc[n][2], acc[n][3]);
            }
            if (t == 0) {
                Af[(it & 1) * 64 + r0] = a0;
                Af[(it & 1) * 64 + r1] = a1;
                if (it == 15) { Lf[r0] = l0; Lf[r1] = l1; }
            }

            // tensor PV slice: cols 96..127
#pragma unroll
            for (int n = 0; n < 4; n++) {
                osl[n][0] *= a0; osl[n][1] *= a0;
                osl[n][2] *= a1; osl[n][3] *= a1;
            }
            u32 vsb = smb + VSL + (it & 1) * 5120;
#pragma unroll
            for (int kk = 0; kk < 4; kk++) {
                u32 pa[4];
                pa[0] = packh2(acc[2 * kk][0],     acc[2 * kk][1]);
                pa[1] = packh2(acc[2 * kk][2],     acc[2 * kk][3]);
                pa[2] = packh2(acc[2 * kk + 1][0], acc[2 * kk + 1][1]);
                pa[3] = packh2(acc[2 * kk + 1][2], acc[2 * kk + 1][3]);
                u32 vb0[4], vb1[4];
                u32 base = vsb + (kk * 16 + (lane & 15)) * 80 + ((lane >> 4) << 4);
                ldsm_x4_t(vb0, base);
                ldsm_x4_t(vb1, base + 32);
                mma_f16(osl[0], pa, vb0);
                mma_f16(osl[1], pa, vb0 + 2);
                mma_f16(osl[2], pa, vb1);
                mma_f16(osl[3], pa, vb1 + 2);
            }
        }

        if (!isS && it > 0) {
            int j = it - 1;
            if (it < 16) {
                u32 vd = smb + AVS + (it & 1) * 32768;
#pragma unroll
                for (int jj = 0; jj < 16; jj++) {
                    int q = vt + jj * 128;
                    int r = q >> 5, c = q & 31;
                    cp16(vd + r * 512 + c * 16,
                         Vg + (size_t)(it * 64 + r) * VSTR + c * 4);
                }
                cp_commit();
            }
            const float* Pb = Pf + (j & 1) * (64 * 68);
            const char* Vb = sm + AVS + (j & 1) * 32768;
#pragma unroll
            for (int ii = 0; ii < 8; ii++) {
                float a = Af[(j & 1) * 64 + ty * 8 + ii];
                u64 ad = pack2(a, a);
#pragma unroll
                for (int c = 0; c < 3; c++) O2[ii][c] = mul2(O2[ii][c], ad);
            }
#pragma unroll 2
            for (int j4 = 0; j4 < 16; j4++) {
                float pv[8][4];
#pragma unroll
                for (int ii = 0; ii < 8; ii++) {
                    float4 tmp = *(const float4*)&Pb[(ty * 8 + ii) * 68 + j4 * 4];
                    pv[ii][0] = tmp.x; pv[ii][1] = tmp.y;
                    pv[ii][2] = tmp.z; pv[ii][3] = tmp.w;
                }
#pragma unroll
                for (int e = 0; e < 4; e++) {
                    const u64* vr = (const u64*)(Vb + ((j4 * 4 + e) * 128 + tx * 6) * 4);
                    u64 v0 = vr[0], v1 = vr[1], v2 = vr[2];
#pragma unroll
                    for (int ii = 0; ii < 8; ii++) {
                        u64 pd = pack2(pv[ii][e], pv[ii][e]);
                        fma2(O2[ii][0], pd, v0);
                        fma2(O2[ii][1], pd, v1);
                        fma2(O2[ii][2], pd, v2);
                    }
                }
            }
        }
    }

    if (isS) {
        // S-warp epilogue: cols 96..127, plain fp16
        float inv0 = 1.0f / l0, inv1 = 1.0f / l1;
        int gr0 = seg * SEGLEN + qt * 64 + warp * 16 + g;
#pragma unroll
        for (int n = 0; n < 4; n++) {
            int col = h * HD + 96 + n * 8 + t * 2;
            *(u32*)(o2 + (size_t)gr0 * OD + col) =
                packh2(osl[n][0] * inv0, osl[n][1] * inv0);
            *(u32*)(o2 + (size_t)(gr0 + 8) * OD + col) =
                packh2(osl[n][2] * inv1, osl[n][3] * inv1);
        }
    } else {
        // V-warp epilogue: cols 0..95, plain fp16
#pragma unroll
        for (int ii = 0; ii < 8; ii++) {
            int row = ty * 8 + ii;
            float inv = 1.0f / Lf[row];
            f16* orow = o2 + (size_t)(seg * SEGLEN + qt * 64 + row) * OD + h * HD + tx * 6;
#pragma unroll
            for (int c = 0; c < 3; c++) {
                float lo, hi; unpack2(O2[ii][c], lo, hi);
                *(u32*)(orow + 2 * c) = packh2(lo * inv, hi * inv);
            }
        }
    }
}

// ---------------------------------------------------------------------------
extern "C" void kernel_launch(void* const* d_in, const int* in_sizes, int n_in,
                              void* d_out, int out_size)
{
    const float* x    = (const float*)d_in[0];
    const float* cosT = (const float*)d_in[2];
    const float* sinT = (const float*)d_in[3];
    const float* Wq   = (const float*)d_in[4];
    const float* Wk   = (const float*)d_in[5];
    const float* Wv   = (const float*)d_in[6];
    const float* Wo   = (const float*)d_in[7];
    const float* qw   = (const float*)d_in[8];
    const float* kw   = (const float*)d_in[9];
    float* out = (float*)d_out;

    f16 *x2, *w2, *o2, *wo2, *vhp;
    bf16 *qsp, *ksp;
    float *vp;
    cudaGetSymbolAddress((void**)&x2,  g_x2);
    cudaGetSymbolAddress((void**)&w2,  g_w2);
    cudaGetSymbolAddress((void**)&o2,  g_o2);
    cudaGetSymbolAddress((void**)&wo2, g_wo2);
    cudaGetSymbolAddress((void**)&qsp, g_qs);
    cudaGetSymbolAddress((void**)&ksp, g_ks);
    cudaGetSymbolAddress((void**)&vp,  g_v);
    cudaGetSymbolAddress((void**)&vhp, g_vh);

    cudaFuncSetAttribute(gemm_mma,
        cudaFuncAttributeMaxDynamicSharedMemorySize, GEMM_SMEM);
    cudaFuncSetAttribute(attn_tc,
        cudaFuncAttributeMaxDynamicSharedMemorySize, ATT_SMEM);

    // launches 0-4: plain fp16 conversions (launch 5 = QKV gemm for ncu)
    {
        int t8 = S_TOK * HID / 8;
        cvt_f16<<<(t8 + 255) / 256, 256>>>(x, x2, t8);
        t8 = 2048 * HID / 8;
        cvt_f16<<<(t8 + 255) / 256, 256>>>(Wq, w2, t8);
        t8 = 1024 * HID / 8;
        cvt_f16<<<(t8 + 255) / 256, 256>>>(Wk, w2 + (size_t)2048 * HID, t8);
        cvt_f16<<<(t8 + 255) / 256, 256>>>(Wv, w2 + (size_t)3072 * HID, t8);
        t8 = HID * OD / 8;
        cvt_f16<<<(t8 + 255) / 256, 256>>>(Wo, wo2, t8);
    }

    // QKV projection (fp16 1-term) with fused RMSNorm+RoPE / V-split epilogue
    gemm_mma<<<dim3(QKVD / 128, S_TOK / 128), 256, GEMM_SMEM>>>(
        x2, w2, nullptr, QKVD, HID, 1, qsp, ksp, vp, vhp, cosT, sinT, qw, kw);

    // hybrid tensor/fma attention -> fp16 output
    attn_tc<<<dim3(16, 8, 16), 256, ATT_SMEM>>>(qsp, ksp, vp, vhp, o2);

    // output projection (fp16 1-term) -> d_out
    gemm_mma<<<dim3(HID / 128, S_TOK / 128), 256, GEMM_SMEM>>>(
        o2, wo2, out, HID, OD, 0, nullptr, nullptr, nullptr, nullptr,
        nullptr, nullptr, nullptr, nullptr);
}